// round 1
// baseline (speedup 1.0000x reference)
#include <cuda_runtime.h>
#include <mma.h>

using namespace nvcuda;

#define DIM    1024
#define HEADS  16
#define DK     64
#define BATCH  8
#define NT     512
#define NV     1024
#define BH     (BATCH*HEADS)

// ---------------- scratch (static device globals; allocation-free) ----------
__device__ float g_tn[BATCH*NT*DIM];   // normalized text
__device__ float g_vn[BATCH*NV*DIM];   // normalized vision
__device__ float g_tq[BH*NT*DK];
__device__ float g_tk[BH*NT*DK];
__device__ float g_tv[BH*NT*DK];
__device__ float g_vq[BH*NV*DK];
__device__ float g_vk[BH*NV*DK];
__device__ float g_vv[BH*NV*DK];

// ---------------- LayerNorm: one block per row of 1024 ----------------------
__global__ void ln_kernel(const float* __restrict__ x, const float* __restrict__ g,
                          const float* __restrict__ b, float* __restrict__ y)
{
    int row = blockIdx.x;
    int t = threadIdx.x;                       // 256 threads, 4 floats each
    const float4* xr = (const float4*)(x + (size_t)row * DIM);
    float4 xv = xr[t];

    float s  = xv.x + xv.y + xv.z + xv.w;
    float sq = xv.x*xv.x + xv.y*xv.y + xv.z*xv.z + xv.w*xv.w;

    __shared__ float red[16];
    #pragma unroll
    for (int o = 16; o; o >>= 1) {
        s  += __shfl_xor_sync(0xffffffffu, s,  o);
        sq += __shfl_xor_sync(0xffffffffu, sq, o);
    }
    int wid = t >> 5, lid = t & 31;
    if (lid == 0) { red[wid] = s; red[8 + wid] = sq; }
    __syncthreads();
    if (t == 0) {
        float S = 0.f, SQ = 0.f;
        #pragma unroll
        for (int i = 0; i < 8; i++) { S += red[i]; SQ += red[8 + i]; }
        red[0] = S; red[8] = SQ;
    }
    __syncthreads();
    float mu  = red[0] * (1.f / DIM);
    float var = red[8] * (1.f / DIM) - mu * mu;
    float inv = rsqrtf(var + 1e-5f);

    float4 gv = ((const float4*)g)[t];
    float4 bv = ((const float4*)b)[t];
    float4 o;
    o.x = (xv.x - mu) * inv * gv.x + bv.x;
    o.y = (xv.y - mu) * inv * gv.y + bv.y;
    o.z = (xv.z - mu) * inv * gv.z + bv.z;
    o.w = (xv.w - mu) * inv * gv.w + bv.w;
    ((float4*)(y + (size_t)row * DIM))[t] = o;
}

// ---------------- Projection GEMM: C = X @ W^T + bias, scattered to heads ---
// X: [M,1024] row-major.  W: [1024,1024] row-major (torch Linear weight).
// out[((b*16+h)*seqlen + n)*64 + d]  with gr = b*seqlen+n, col = h*64+d.
// Block tile 128x64, BK=32, 8 warps (4x2), warp tile 32x32, tf32 WMMA.
__global__ void proj_kernel(const float* __restrict__ X, const float* __restrict__ W,
                            const float* __restrict__ bias, float* __restrict__ out,
                            int seqlen)
{
    extern __shared__ float smem[];
    float* Ash = smem;             // 128*32
    float* Bsh = smem + 128 * 32;  // 64*32
    float* Csh = smem;             // alias, 128*64 (used after k-loop)

    int t = threadIdx.x;           // 256
    int row0 = blockIdx.y * 128;
    int col0 = blockIdx.x * 64;
    int wid = t >> 5;
    int warpM = wid >> 1;          // 0..3
    int warpN = wid & 1;           // 0..1

    wmma::fragment<wmma::accumulator, 16, 16, 8, float> acc[2][2];
    #pragma unroll
    for (int mi = 0; mi < 2; mi++)
        #pragma unroll
        for (int nj = 0; nj < 2; nj++)
            wmma::fill_fragment(acc[mi][nj], 0.0f);

    for (int k0 = 0; k0 < DIM; k0 += 32) {
        // stage A tile 128x32 (tf32-converted)
        #pragma unroll
        for (int i = 0; i < 4; i++) {
            int f = t + i * 256;             // 0..1023 float4s
            int r = f >> 3, c = (f & 7) * 4;
            float4 v = *(const float4*)(X + (size_t)(row0 + r) * DIM + k0 + c);
            float* d = Ash + r * 32 + c;
            d[0] = wmma::__float_to_tf32(v.x);
            d[1] = wmma::__float_to_tf32(v.y);
            d[2] = wmma::__float_to_tf32(v.z);
            d[3] = wmma::__float_to_tf32(v.w);
        }
        // stage B tile: W rows [col0..col0+63], k slice -> Bsh[j][k]
        #pragma unroll
        for (int i = 0; i < 2; i++) {
            int f = t + i * 256;             // 0..511 float4s
            int r = f >> 3, c = (f & 7) * 4;
            float4 v = *(const float4*)(W + (size_t)(col0 + r) * DIM + k0 + c);
            float* d = Bsh + r * 32 + c;
            d[0] = wmma::__float_to_tf32(v.x);
            d[1] = wmma::__float_to_tf32(v.y);
            d[2] = wmma::__float_to_tf32(v.z);
            d[3] = wmma::__float_to_tf32(v.w);
        }
        __syncthreads();

        #pragma unroll
        for (int kk = 0; kk < 4; kk++) {
            wmma::fragment<wmma::matrix_a, 16, 16, 8, wmma::precision::tf32, wmma::row_major> a[2];
            wmma::fragment<wmma::matrix_b, 16, 16, 8, wmma::precision::tf32, wmma::col_major> bf[2];
            #pragma unroll
            for (int mi = 0; mi < 2; mi++)
                wmma::load_matrix_sync(a[mi], Ash + (warpM * 32 + mi * 16) * 32 + kk * 8, 32);
            #pragma unroll
            for (int nj = 0; nj < 2; nj++)
                wmma::load_matrix_sync(bf[nj], Bsh + (warpN * 32 + nj * 16) * 32 + kk * 8, 32);
            #pragma unroll
            for (int mi = 0; mi < 2; mi++)
                #pragma unroll
                for (int nj = 0; nj < 2; nj++)
                    wmma::mma_sync(acc[mi][nj], a[mi], bf[nj], acc[mi][nj]);
        }
        __syncthreads();
    }

    // stage C to shared, then bias + head scatter
    #pragma unroll
    for (int mi = 0; mi < 2; mi++)
        #pragma unroll
        for (int nj = 0; nj < 2; nj++)
            wmma::store_matrix_sync(Csh + (warpM * 32 + mi * 16) * 64 + warpN * 32 + nj * 16,
                                    acc[mi][nj], 64, wmma::mem_row_major);
    __syncthreads();

    #pragma unroll
    for (int i = 0; i < 8; i++) {
        int f = t + i * 256;                 // 0..2047 float4s over 128x64
        int r = f >> 4, c = (f & 15) * 4;
        float4 v = *(float4*)(Csh + r * 64 + c);
        int jg = col0 + c;
        float4 bb = *(const float4*)(bias + jg);
        v.x += bb.x; v.y += bb.y; v.z += bb.z; v.w += bb.w;
        int gr = row0 + r;
        int bidx = gr / seqlen;
        int n = gr - bidx * seqlen;
        int h = jg >> 6;
        int d = jg & 63;
        *(float4*)(out + ((size_t)(bidx * HEADS + h) * seqlen + n) * DK + d) = v;
    }
}

// ---------------- Fused flash cross-attention ------------------------------
// grid (nq/64, BH), 128 threads (4 warps). Q block 64 rows, KV chunks of 64.
// Online softmax; O accumulator lives in shared so per-row rescale works.
__global__ void attn_kernel(const float* __restrict__ Qg, const float* __restrict__ Kg,
                            const float* __restrict__ Vg, float* __restrict__ out,
                            int nq, int nk)
{
    extern __shared__ float smem[];
    float* Qsh = smem;            // 64*64 (tf32)
    float* Ksh = Qsh + 4096;      // 64*64 (tf32)
    float* Vsh = Ksh + 4096;      // 64*64 (tf32)
    float* Ssh = Vsh + 4096;      // 64*64 scores -> P (tf32)
    float* Osh = Ssh + 4096;      // 64*64 fp32 accumulator
    float* msh = Osh + 4096;      // 64
    float* lsh = msh + 64;        // 64

    int t = threadIdx.x;          // 128
    int wid = t >> 5;             // warp owns rows [wid*16, wid*16+16)
    int bh = blockIdx.y;
    int q0 = blockIdx.x * 64;

    const float* Qb = Qg + ((size_t)bh * nq + q0) * DK;
    const float* Kb = Kg + (size_t)bh * nk * DK;
    const float* Vb = Vg + (size_t)bh * nk * DK;

    // load Q (tf32) + init O/m/l
    #pragma unroll
    for (int i = 0; i < 8; i++) {
        int f = t + i * 128;                 // 0..1023 float4s
        float4 v = ((const float4*)Qb)[f];
        float* d = Qsh + f * 4;
        d[0] = wmma::__float_to_tf32(v.x);
        d[1] = wmma::__float_to_tf32(v.y);
        d[2] = wmma::__float_to_tf32(v.z);
        d[3] = wmma::__float_to_tf32(v.w);
        ((float4*)Osh)[f] = make_float4(0.f, 0.f, 0.f, 0.f);
    }
    if (t < 64) { msh[t] = -1e30f; lsh[t] = 0.f; }
    __syncthreads();

    int nchunks = nk >> 6;
    for (int c = 0; c < nchunks; c++) {
        const float4* Kc = (const float4*)(Kb + (size_t)c * 64 * DK);
        const float4* Vc = (const float4*)(Vb + (size_t)c * 64 * DK);
        #pragma unroll
        for (int i = 0; i < 8; i++) {
            int f = t + i * 128;
            float4 kv = Kc[f];
            float* d = Ksh + f * 4;
            d[0] = wmma::__float_to_tf32(kv.x);
            d[1] = wmma::__float_to_tf32(kv.y);
            d[2] = wmma::__float_to_tf32(kv.z);
            d[3] = wmma::__float_to_tf32(kv.w);
            float4 vv = Vc[f];
            float* e = Vsh + f * 4;
            e[0] = wmma::__float_to_tf32(vv.x);
            e[1] = wmma::__float_to_tf32(vv.y);
            e[2] = wmma::__float_to_tf32(vv.z);
            e[3] = wmma::__float_to_tf32(vv.w);
        }
        __syncthreads();

        // S = (Q @ K^T) * scale ; each warp: 16 rows x 64 cols
        wmma::fragment<wmma::accumulator, 16, 16, 8, float> sacc[4];
        #pragma unroll
        for (int j = 0; j < 4; j++) wmma::fill_fragment(sacc[j], 0.0f);
        #pragma unroll
        for (int kk = 0; kk < 8; kk++) {
            wmma::fragment<wmma::matrix_a, 16, 16, 8, wmma::precision::tf32, wmma::row_major> a;
            wmma::load_matrix_sync(a, Qsh + wid * 16 * 64 + kk * 8, 64);
            #pragma unroll
            for (int j = 0; j < 4; j++) {
                wmma::fragment<wmma::matrix_b, 16, 16, 8, wmma::precision::tf32, wmma::col_major> bf;
                wmma::load_matrix_sync(bf, Ksh + j * 16 * 64 + kk * 8, 64);
                wmma::mma_sync(sacc[j], a, bf, sacc[j]);
            }
        }
        const float scale = 0.125f;          // 1/sqrt(64)
        #pragma unroll
        for (int j = 0; j < 4; j++) {
            #pragma unroll
            for (int e = 0; e < sacc[j].num_elements; e++) sacc[j].x[e] *= scale;
            wmma::store_matrix_sync(Ssh + wid * 16 * 64 + j * 16, sacc[j], 64, wmma::mem_row_major);
        }
        __syncthreads();

        // online softmax (row-parallel over threads 0..63)
        if (t < 64) {
            float* Sr = Ssh + t * 64;
            float m = msh[t];
            float mx = m;
            #pragma unroll 8
            for (int j = 0; j < 64; j++) mx = fmaxf(mx, Sr[j]);
            float alpha = __expf(m - mx);
            float sum = 0.f;
            #pragma unroll 8
            for (int j = 0; j < 64; j++) {
                float p = __expf(Sr[j] - mx);
                sum += p;
                Sr[j] = wmma::__float_to_tf32(p);
            }
            lsh[t] = lsh[t] * alpha + sum;
            msh[t] = mx;
            float* Or = Osh + t * 64;
            #pragma unroll 8
            for (int j = 0; j < 64; j++) Or[j] *= alpha;
        }
        __syncthreads();

        // O += P @ V
        wmma::fragment<wmma::accumulator, 16, 16, 8, float> oacc[4];
        #pragma unroll
        for (int j = 0; j < 4; j++)
            wmma::load_matrix_sync(oacc[j], Osh + wid * 16 * 64 + j * 16, 64, wmma::mem_row_major);
        #pragma unroll
        for (int kk = 0; kk < 8; kk++) {
            wmma::fragment<wmma::matrix_a, 16, 16, 8, wmma::precision::tf32, wmma::row_major> a;
            wmma::load_matrix_sync(a, Ssh + wid * 16 * 64 + kk * 8, 64);
            #pragma unroll
            for (int j = 0; j < 4; j++) {
                wmma::fragment<wmma::matrix_b, 16, 16, 8, wmma::precision::tf32, wmma::row_major> bf;
                wmma::load_matrix_sync(bf, Vsh + kk * 8 * 64 + j * 16, 64);
                wmma::mma_sync(oacc[j], a, bf, oacc[j]);
            }
        }
        #pragma unroll
        for (int j = 0; j < 4; j++)
            wmma::store_matrix_sync(Osh + wid * 16 * 64 + j * 16, oacc[j], 64, wmma::mem_row_major);
        __syncthreads();
    }

    // epilogue: divide by l, merge heads: out[(b*nq + q)*1024 + h*64 + d]
    int b = bh >> 4, h = bh & 15;
    float* ob = out + ((size_t)(b * nq) + q0) * DIM + h * DK;
    #pragma unroll
    for (int i = 0; i < 8; i++) {
        int f = t + i * 128;                 // 0..1023 float4s over 64x64
        int r = f >> 4, cc = (f & 15) * 4;
        float inv = 1.f / lsh[r];
        float4 v = *(float4*)(Osh + r * 64 + cc);
        v.x *= inv; v.y *= inv; v.z *= inv; v.w *= inv;
        *(float4*)(ob + (size_t)r * DIM + cc) = v;
    }
}

// ---------------- host launch ----------------------------------------------
extern "C" void kernel_launch(void* const* d_in, const int* in_sizes, int n_in,
                              void* d_out, int out_size)
{
    (void)in_sizes; (void)n_in; (void)out_size;
    const float* text   = (const float*)d_in[0];
    const float* vision = (const float*)d_in[1];
    const float* n1g = (const float*)d_in[2];
    const float* n1b = (const float*)d_in[3];
    const float* n2g = (const float*)d_in[4];
    const float* n2b = (const float*)d_in[5];
    const float* Wq1 = (const float*)d_in[6];
    const float* bq1 = (const float*)d_in[7];
    const float* Wk1 = (const float*)d_in[8];
    const float* bk1 = (const float*)d_in[9];
    const float* Wv1 = (const float*)d_in[10];
    const float* bv1 = (const float*)d_in[11];
    const float* Wq2 = (const float*)d_in[12];
    const float* bq2 = (const float*)d_in[13];
    const float* Wk2 = (const float*)d_in[14];
    const float* bk2 = (const float*)d_in[15];
    const float* Wv2 = (const float*)d_in[16];
    const float* bv2 = (const float*)d_in[17];
    float* out = (float*)d_out;

    float *tn, *vn, *tq, *tk, *tv, *vq, *vk, *vv;
    cudaGetSymbolAddress((void**)&tn, g_tn);
    cudaGetSymbolAddress((void**)&vn, g_vn);
    cudaGetSymbolAddress((void**)&tq, g_tq);
    cudaGetSymbolAddress((void**)&tk, g_tk);
    cudaGetSymbolAddress((void**)&tv, g_tv);
    cudaGetSymbolAddress((void**)&vq, g_vq);
    cudaGetSymbolAddress((void**)&vk, g_vk);
    cudaGetSymbolAddress((void**)&vv, g_vv);

    const size_t A1 = (size_t)BATCH * NT * DIM;     // 4,194,304
    const size_t A2 = (size_t)BATCH * NV * DIM;     // 8,388,608

    // residual passthrough (independent of the compute chain)
    cudaMemcpyAsync(out + A1 + A2,      text,   A1 * sizeof(float), cudaMemcpyDeviceToDevice, 0);
    cudaMemcpyAsync(out + A1 + A2 + A1, vision, A2 * sizeof(float), cudaMemcpyDeviceToDevice, 0);

    ln_kernel<<<BATCH * NT, 256>>>(text,   n1g, n1b, tn);
    ln_kernel<<<BATCH * NV, 256>>>(vision, n2g, n2b, vn);

    const int psmem = 128 * 64 * sizeof(float);     // 32 KB (C tile dominates)
    dim3 gt(DIM / 64, BATCH * NT / 128);            // 16 x 32
    dim3 gv(DIM / 64, BATCH * NV / 128);            // 16 x 64
    proj_kernel<<<gt, 256, psmem>>>(tn, Wq1, bq1, tq, NT);
    proj_kernel<<<gt, 256, psmem>>>(tn, Wk1, bk1, tk, NT);
    proj_kernel<<<gt, 256, psmem>>>(tn, Wv1, bv1, tv, NT);
    proj_kernel<<<gv, 256, psmem>>>(vn, Wq2, bq2, vq, NV);
    proj_kernel<<<gv, 256, psmem>>>(vn, Wk2, bk2, vk, NV);
    proj_kernel<<<gv, 256, psmem>>>(vn, Wv2, bv2, vv, NV);

    const int asmem = (5 * 4096 + 128) * sizeof(float);   // 82,432 B
    cudaFuncSetAttribute(attn_kernel, cudaFuncAttributeMaxDynamicSharedMemorySize, asmem);
    attn_kernel<<<dim3(NT / 64, BH), 128, asmem>>>(tq, vk, vv, out,      NT, NV);
    attn_kernel<<<dim3(NV / 64, BH), 128, asmem>>>(vq, tk, tv, out + A1, NV, NT);
}

// round 2
// speedup vs baseline: 2.0802x; 2.0802x over previous
#include <cuda_runtime.h>
#include <mma.h>

using namespace nvcuda;

#define DIM    1024
#define HEADS  16
#define DK     64
#define BATCH  8
#define NT     512
#define NV     1024
#define BH     (BATCH*HEADS)

// ---------------- scratch (static device globals; allocation-free) ----------
__device__ float g_tn[BATCH*NT*DIM];
__device__ float g_vn[BATCH*NV*DIM];
__device__ float g_tq[BH*NT*DK];
__device__ float g_tk[BH*NT*DK];
__device__ float g_tv[BH*NT*DK];
__device__ float g_vq[BH*NV*DK];
__device__ float g_vk[BH*NV*DK];
__device__ float g_vv[BH*NV*DK];
__device__ float g_wc[6*DIM*DIM];     // tf32-rounded weights

// ---------------- cp.async helpers -----------------------------------------
__device__ __forceinline__ void cp_async16(void* smem, const void* gmem) {
    unsigned s = (unsigned)__cvta_generic_to_shared(smem);
    asm volatile("cp.async.ca.shared.global [%0], [%1], 16;\n" :: "r"(s), "l"(gmem));
}
__device__ __forceinline__ void cp_commit() { asm volatile("cp.async.commit_group;\n"); }
template<int N> __device__ __forceinline__ void cp_wait() {
    asm volatile("cp.async.wait_group %0;\n" :: "n"(N));
}

// ---------------- tf32 RN weight conversion ---------------------------------
__global__ void tf32_conv_kernel(const float* __restrict__ src, float* __restrict__ dst)
{
    int i = blockIdx.x * blockDim.x + threadIdx.x;   // over float4s
    float4 v = ((const float4*)src)[i];
    v.x = wmma::__float_to_tf32(v.x);
    v.y = wmma::__float_to_tf32(v.y);
    v.z = wmma::__float_to_tf32(v.z);
    v.w = wmma::__float_to_tf32(v.w);
    ((float4*)dst)[i] = v;
}

// ---------------- LayerNorm (tf32-rounded output) ---------------------------
__global__ void ln_kernel(const float* __restrict__ x, const float* __restrict__ g,
                          const float* __restrict__ b, float* __restrict__ y)
{
    int row = blockIdx.x;
    int t = threadIdx.x;                       // 256 threads, 4 floats each
    const float4* xr = (const float4*)(x + (size_t)row * DIM);
    float4 xv = xr[t];

    float s  = xv.x + xv.y + xv.z + xv.w;
    float sq = xv.x*xv.x + xv.y*xv.y + xv.z*xv.z + xv.w*xv.w;

    __shared__ float red[16];
    #pragma unroll
    for (int o = 16; o; o >>= 1) {
        s  += __shfl_xor_sync(0xffffffffu, s,  o);
        sq += __shfl_xor_sync(0xffffffffu, sq, o);
    }
    int wid = t >> 5, lid = t & 31;
    if (lid == 0) { red[wid] = s; red[8 + wid] = sq; }
    __syncthreads();
    if (t == 0) {
        float S = 0.f, SQ = 0.f;
        #pragma unroll
        for (int i = 0; i < 8; i++) { S += red[i]; SQ += red[8 + i]; }
        red[0] = S; red[8] = SQ;
    }
    __syncthreads();
    float mu  = red[0] * (1.f / DIM);
    float var = red[8] * (1.f / DIM) - mu * mu;
    float inv = rsqrtf(var + 1e-5f);

    float4 gv = ((const float4*)g)[t];
    float4 bv = ((const float4*)b)[t];
    float4 o;
    o.x = wmma::__float_to_tf32((xv.x - mu) * inv * gv.x + bv.x);
    o.y = wmma::__float_to_tf32((xv.y - mu) * inv * gv.y + bv.y);
    o.z = wmma::__float_to_tf32((xv.z - mu) * inv * gv.z + bv.z);
    o.w = wmma::__float_to_tf32((xv.w - mu) * inv * gv.w + bv.w);
    ((float4*)(y + (size_t)row * DIM))[t] = o;
}

// ---------------- Projection GEMM v2 ----------------------------------------
// C = X @ W^T + bias, head-scattered. 128x128x16 tiles, cp.async double-buffered,
// 8 warps with 32x64 warp tiles, skewed smem (ld=20).
#define PBM 128
#define PBN 128
#define PBK 16
#define PLD 20

__global__ __launch_bounds__(256) void proj_kernel(
    const float* __restrict__ X, const float* __restrict__ W,
    const float* __restrict__ bias, float* __restrict__ out, int seqlen)
{
    extern __shared__ float sm[];
    float* As0 = sm;
    float* As1 = sm + PBM*PLD;
    float* Bs0 = sm + 2*PBM*PLD;
    float* Bs1 = sm + 2*PBM*PLD + PBN*PLD;
    float* Csh = sm;                        // epilogue alias, ld=132

    int t = threadIdx.x;
    int row0 = blockIdx.y * PBM;
    int col0 = blockIdx.x * PBN;
    int wid = t >> 5;
    int warpM = wid >> 1;                   // 0..3 : 32-row slab
    int warpN = wid & 1;                    // 0..1 : 64-col slab

    wmma::fragment<wmma::accumulator, 16, 16, 8, float> acc[2][4];
    #pragma unroll
    for (int mi = 0; mi < 2; mi++)
        #pragma unroll
        for (int nj = 0; nj < 4; nj++)
            wmma::fill_fragment(acc[mi][nj], 0.0f);

    auto stage = [&](float* Ad, float* Bd, int k0) {
        #pragma unroll
        for (int i = 0; i < 2; i++) {
            int f = t + i * 256;            // 0..511
            int r = f >> 2, c = (f & 3) * 4;
            cp_async16(Ad + r*PLD + c, X + (size_t)(row0 + r)*DIM + k0 + c);
            cp_async16(Bd + r*PLD + c, W + (size_t)(col0 + r)*DIM + k0 + c);
        }
    };

    stage(As0, Bs0, 0);
    cp_commit();

    #pragma unroll 1
    for (int kt = 0; kt < DIM/PBK; kt++) {
        float* A = (kt & 1) ? As1 : As0;
        float* B = (kt & 1) ? Bs1 : Bs0;
        if (kt + 1 < DIM/PBK) {
            stage((kt & 1) ? As0 : As1, (kt & 1) ? Bs0 : Bs1, (kt + 1) * PBK);
            cp_commit();
            cp_wait<1>();
        } else {
            cp_wait<0>();
        }
        __syncthreads();

        #pragma unroll
        for (int kk = 0; kk < 2; kk++) {
            wmma::fragment<wmma::matrix_a, 16, 16, 8, wmma::precision::tf32, wmma::row_major> a[2];
            wmma::fragment<wmma::matrix_b, 16, 16, 8, wmma::precision::tf32, wmma::col_major> bf[4];
            #pragma unroll
            for (int mi = 0; mi < 2; mi++)
                wmma::load_matrix_sync(a[mi], A + (warpM*32 + mi*16)*PLD + kk*8, PLD);
            #pragma unroll
            for (int nj = 0; nj < 4; nj++)
                wmma::load_matrix_sync(bf[nj], B + (warpN*64 + nj*16)*PLD + kk*8, PLD);
            #pragma unroll
            for (int mi = 0; mi < 2; mi++)
                #pragma unroll
                for (int nj = 0; nj < 4; nj++)
                    wmma::mma_sync(acc[mi][nj], a[mi], bf[nj], acc[mi][nj]);
        }
        __syncthreads();
    }

    // epilogue: frags -> Csh -> bias + tf32 round + head scatter
    #pragma unroll
    for (int mi = 0; mi < 2; mi++)
        #pragma unroll
        for (int nj = 0; nj < 4; nj++)
            wmma::store_matrix_sync(Csh + (warpM*32 + mi*16)*132 + warpN*64 + nj*16,
                                    acc[mi][nj], 132, wmma::mem_row_major);
    __syncthreads();

    #pragma unroll
    for (int i = 0; i < 16; i++) {
        int f = t + i * 256;                // 0..4095 float4s over 128x128
        int r = f >> 5, c = (f & 31) * 4;
        float4 v = *(float4*)(Csh + r*132 + c);
        int jg = col0 + c;
        float4 bb = *(const float4*)(bias + jg);
        v.x = wmma::__float_to_tf32(v.x + bb.x);
        v.y = wmma::__float_to_tf32(v.y + bb.y);
        v.z = wmma::__float_to_tf32(v.z + bb.z);
        v.w = wmma::__float_to_tf32(v.w + bb.w);
        int gr = row0 + r;
        int bidx = gr / seqlen;
        int n = gr - bidx * seqlen;
        int h = jg >> 6;
        int d = jg & 63;
        *(float4*)(out + ((size_t)(bidx * HEADS + h) * seqlen + n) * DK + d) = v;
    }
}

// ---------------- Fused flash cross-attention v2 ----------------------------
// Q tile 128, KV chunks 64 (cp.async double-buffered), 256 threads / 8 warps.
#define ALD 68
// smem float offsets
#define OFF_Q   0
#define OFF_K   (128*ALD)                  // 8704
#define OFF_V   (OFF_K + 2*64*ALD)         // 17408
#define OFF_S   (OFF_V + 2*64*ALD)         // 26112
#define OFF_O   (OFF_S + 128*ALD)          // 34816
#define OFF_M   (OFF_O + 128*ALD)          // 43520
#define OFF_L   (OFF_M + 128)
#define OFF_A   (OFF_L + 128)
#define ATT_SMEM ((OFF_A + 128) * 4)       // 175,616 B

__global__ __launch_bounds__(256) void attn_kernel(
    const float* __restrict__ Qg, const float* __restrict__ Kg,
    const float* __restrict__ Vg, float* __restrict__ out, int nq, int nk)
{
    extern __shared__ float sm[];
    float* Qsh = sm + OFF_Q;
    float* Ksh[2] = { sm + OFF_K, sm + OFF_K + 64*ALD };
    float* Vsh[2] = { sm + OFF_V, sm + OFF_V + 64*ALD };
    float* Ssh = sm + OFF_S;
    float* Osh = sm + OFF_O;
    float* msh = sm + OFF_M;
    float* lsh = sm + OFF_L;
    float* ash = sm + OFF_A;

    int t = threadIdx.x;
    int w = t >> 5;                         // warp: 16 q-rows
    int bh = blockIdx.y;
    int q0 = blockIdx.x * 128;

    const float* Qb = Qg + ((size_t)bh * nq + q0) * DK;
    const float* Kb = Kg + (size_t)bh * nk * DK;
    const float* Vb = Vg + (size_t)bh * nk * DK;

    // prologue: async-load Q tile + KV chunk 0
    #pragma unroll
    for (int i = 0; i < 8; i++) {
        int f = t + i * 256;                // 0..2047
        int r = f >> 4, c = (f & 15) * 4;
        cp_async16(Qsh + r*ALD + c, Qb + (size_t)r*DK + c);
    }
    #pragma unroll
    for (int i = 0; i < 4; i++) {
        int f = t + i * 256;                // 0..1023
        int r = f >> 4, c = (f & 15) * 4;
        cp_async16(Ksh[0] + r*ALD + c, Kb + (size_t)r*DK + c);
        cp_async16(Vsh[0] + r*ALD + c, Vb + (size_t)r*DK + c);
    }
    cp_commit();

    // init O / m / l
    #pragma unroll
    for (int i = 0; i < 8; i++) {
        int f = t + i * 256;
        int r = f >> 4, c = (f & 15) * 4;
        *(float4*)(Osh + r*ALD + c) = make_float4(0.f, 0.f, 0.f, 0.f);
    }
    if (t < 128) { msh[t] = -1e30f; lsh[t] = 0.f; }

    int nch = nk >> 6;
    #pragma unroll 1
    for (int c = 0; c < nch; c++) {
        int buf = c & 1;
        if (c + 1 < nch) {
            const float* Kc = Kb + (size_t)(c + 1) * 64 * DK;
            const float* Vc = Vb + (size_t)(c + 1) * 64 * DK;
            float* Kd = Ksh[buf ^ 1];
            float* Vd = Vsh[buf ^ 1];
            #pragma unroll
            for (int i = 0; i < 4; i++) {
                int f = t + i * 256;
                int r = f >> 4, cc = (f & 15) * 4;
                cp_async16(Kd + r*ALD + cc, Kc + (size_t)r*DK + cc);
                cp_async16(Vd + r*ALD + cc, Vc + (size_t)r*DK + cc);
            }
            cp_commit();
            cp_wait<1>();
        } else {
            cp_wait<0>();
        }
        __syncthreads();

        // S = (Q @ K^T) * scale : warp w -> rows [w*16, w*16+16), 64 cols
        wmma::fragment<wmma::accumulator, 16, 16, 8, float> sacc[4];
        #pragma unroll
        for (int j = 0; j < 4; j++) wmma::fill_fragment(sacc[j], 0.0f);
        #pragma unroll
        for (int kk = 0; kk < 8; kk++) {
            wmma::fragment<wmma::matrix_a, 16, 16, 8, wmma::precision::tf32, wmma::row_major> a;
            wmma::load_matrix_sync(a, Qsh + (w*16)*ALD + kk*8, ALD);
            #pragma unroll
            for (int j = 0; j < 4; j++) {
                wmma::fragment<wmma::matrix_b, 16, 16, 8, wmma::precision::tf32, wmma::col_major> bf;
                wmma::load_matrix_sync(bf, Ksh[buf] + (j*16)*ALD + kk*8, ALD);
                wmma::mma_sync(sacc[j], a, bf, sacc[j]);
            }
        }
        const float scale = 0.125f;          // 1/sqrt(64)
        #pragma unroll
        for (int j = 0; j < 4; j++) {
            #pragma unroll
            for (int e = 0; e < sacc[j].num_elements; e++) sacc[j].x[e] *= scale;
            wmma::store_matrix_sync(Ssh + (w*16)*ALD + j*16, sacc[j], ALD, wmma::mem_row_major);
        }
        __syncthreads();

        // online softmax: 2 threads per row, 32 cols each; fused O rescale
        {
            int row = t >> 1, half = t & 1;
            float* Sr = Ssh + row*ALD + half*32;
            float mo = msh[row];
            float mx = mo;
            #pragma unroll 8
            for (int j = 0; j < 32; j++) mx = fmaxf(mx, Sr[j]);
            mx = fmaxf(mx, __shfl_xor_sync(0xffffffffu, mx, 1));
            float sum = 0.f;
            #pragma unroll 8
            for (int j = 0; j < 32; j++) {
                float p = __expf(Sr[j] - mx);
                sum += p;
                Sr[j] = wmma::__float_to_tf32(p);
            }
            sum += __shfl_xor_sync(0xffffffffu, sum, 1);
            float alpha = __expf(mo - mx);
            if (half == 0) {
                lsh[row] = lsh[row] * alpha + sum;
                msh[row] = mx;
            }
            // rescale this thread's half of the O row
            float* Or = Osh + row*ALD + half*32;
            #pragma unroll
            for (int j = 0; j < 8; j++) {
                float4 v = *(float4*)(Or + j*4);
                v.x *= alpha; v.y *= alpha; v.z *= alpha; v.w *= alpha;
                *(float4*)(Or + j*4) = v;
            }
        }
        __syncthreads();

        // O += P @ V
        wmma::fragment<wmma::accumulator, 16, 16, 8, float> oacc[4];
        #pragma unroll
        for (int j = 0; j < 4; j++)
            wmma::load_matrix_sync(oacc[j], Osh + (w*16)*ALD + j*16, ALD, wmma::mem_row_major);
        #pragma unroll
        for (int kk = 0; kk < 8; kk++) {
            wmma::fragment<wmma::matrix_a, 16, 16, 8, wmma::precision::tf32, wmma::row_major> a;
            wmma::load_matrix_sync(a, Ssh + (w*16)*ALD + kk*8, ALD);
            #pragma unroll
            for (int j = 0; j < 4; j++) {
                wmma::fragment<wmma::matrix_b, 16, 16, 8, wmma::precision::tf32, wmma::row_major> bf;
                wmma::load_matrix_sync(bf, Vsh[buf] + (kk*8)*ALD + j*16, ALD);
                wmma::mma_sync(oacc[j], a, bf, oacc[j]);
            }
        }
        #pragma unroll
        for (int j = 0; j < 4; j++)
            wmma::store_matrix_sync(Osh + (w*16)*ALD + j*16, oacc[j], ALD, wmma::mem_row_major);
        __syncthreads();
    }

    // epilogue: normalize + merge heads
    int b = bh >> 4, h = bh & 15;
    float* ob = out + ((size_t)(b * nq) + q0) * DIM + h * DK;
    #pragma unroll
    for (int i = 0; i < 8; i++) {
        int f = t + i * 256;
        int r = f >> 4, cc = (f & 15) * 4;
        float inv = 1.f / lsh[r];
        float4 v = *(float4*)(Osh + r*ALD + cc);
        v.x *= inv; v.y *= inv; v.z *= inv; v.w *= inv;
        *(float4*)(ob + (size_t)r * DIM + cc) = v;
    }
}

// ---------------- host launch ------------------------------------------------
extern "C" void kernel_launch(void* const* d_in, const int* in_sizes, int n_in,
                              void* d_out, int out_size)
{
    (void)in_sizes; (void)n_in; (void)out_size;
    const float* text   = (const float*)d_in[0];
    const float* vision = (const float*)d_in[1];
    const float* n1g = (const float*)d_in[2];
    const float* n1b = (const float*)d_in[3];
    const float* n2g = (const float*)d_in[4];
    const float* n2b = (const float*)d_in[5];
    const float* Wq1 = (const float*)d_in[6];
    const float* bq1 = (const float*)d_in[7];
    const float* Wk1 = (const float*)d_in[8];
    const float* bk1 = (const float*)d_in[9];
    const float* Wv1 = (const float*)d_in[10];
    const float* bv1 = (const float*)d_in[11];
    const float* Wq2 = (const float*)d_in[12];
    const float* bq2 = (const float*)d_in[13];
    const float* Wk2 = (const float*)d_in[14];
    const float* bk2 = (const float*)d_in[15];
    const float* Wv2 = (const float*)d_in[16];
    const float* bv2 = (const float*)d_in[17];
    float* out = (float*)d_out;

    float *tn, *vn, *tq, *tk, *tv, *vq, *vk, *vv, *wc;
    cudaGetSymbolAddress((void**)&tn, g_tn);
    cudaGetSymbolAddress((void**)&vn, g_vn);
    cudaGetSymbolAddress((void**)&tq, g_tq);
    cudaGetSymbolAddress((void**)&tk, g_tk);
    cudaGetSymbolAddress((void**)&tv, g_tv);
    cudaGetSymbolAddress((void**)&vq, g_vq);
    cudaGetSymbolAddress((void**)&vk, g_vk);
    cudaGetSymbolAddress((void**)&vv, g_vv);
    cudaGetSymbolAddress((void**)&wc, g_wc);

    const size_t A1 = (size_t)BATCH * NT * DIM;
    const size_t A2 = (size_t)BATCH * NV * DIM;
    const size_t WSZ = (size_t)DIM * DIM;

    // residual passthrough
    cudaMemcpyAsync(out + A1 + A2,      text,   A1 * sizeof(float), cudaMemcpyDeviceToDevice, 0);
    cudaMemcpyAsync(out + A1 + A2 + A1, vision, A2 * sizeof(float), cudaMemcpyDeviceToDevice, 0);

    // tf32 RN-rounded weights (so in-MMA truncation is exact)
    const float* Ws[6] = { Wq1, Wk1, Wv1, Wq2, Wk2, Wv2 };
    for (int i = 0; i < 6; i++)
        tf32_conv_kernel<<<WSZ / (256*4), 256>>>(Ws[i], wc + i * WSZ);

    ln_kernel<<<BATCH * NT, 256>>>(text,   n1g, n1b, tn);
    ln_kernel<<<BATCH * NV, 256>>>(vision, n2g, n2b, vn);

    const int psmem = 128 * 132 * sizeof(float);    // 67,584 B
    cudaFuncSetAttribute(proj_kernel, cudaFuncAttributeMaxDynamicSharedMemorySize, psmem);
    dim3 gt(DIM / PBN, BATCH * NT / PBM);           // 8 x 32
    dim3 gv(DIM / PBN, BATCH * NV / PBM);           // 8 x 64
    proj_kernel<<<gt, 256, psmem>>>(tn, wc + 0*WSZ, bq1, tq, NT);
    proj_kernel<<<gt, 256, psmem>>>(tn, wc + 1*WSZ, bk1, tk, NT);
    proj_kernel<<<gt, 256, psmem>>>(tn, wc + 2*WSZ, bv1, tv, NT);
    proj_kernel<<<gv, 256, psmem>>>(vn, wc + 3*WSZ, bq2, vq, NV);
    proj_kernel<<<gv, 256, psmem>>>(vn, wc + 4*WSZ, bk2, vk, NV);
    proj_kernel<<<gv, 256, psmem>>>(vn, wc + 5*WSZ, bv2, vv, NV);

    cudaFuncSetAttribute(attn_kernel, cudaFuncAttributeMaxDynamicSharedMemorySize, ATT_SMEM);
    attn_kernel<<<dim3(NT / 128, BH), 256, ATT_SMEM>>>(tq, vk, vv, out,      NT, NV);
    attn_kernel<<<dim3(NV / 128, BH), 256, ATT_SMEM>>>(vq, tk, tv, out + A1, NV, NT);
}

// round 3
// speedup vs baseline: 2.4555x; 1.1804x over previous
#include <cuda_runtime.h>
#include <mma.h>

using namespace nvcuda;

#define DIM    1024
#define HEADS  16
#define DK     64
#define BATCH  8
#define NT     512
#define NV     1024
#define BH     (BATCH*HEADS)

// ---------------- scratch (static device globals; allocation-free) ----------
__device__ float g_tn[BATCH*NT*DIM];
__device__ float g_vn[BATCH*NV*DIM];
__device__ float g_tq[BH*NT*DK];
__device__ float g_tk[BH*NT*DK];
__device__ float g_tv[BH*NT*DK];
__device__ float g_vq[BH*NV*DK];
__device__ float g_vk[BH*NV*DK];
__device__ float g_vv[BH*NV*DK];
__device__ float g_wc[6*DIM*DIM];     // tf32-rounded weights

// ---------------- cp.async helpers -----------------------------------------
__device__ __forceinline__ void cp_async16(void* smem, const void* gmem) {
    unsigned s = (unsigned)__cvta_generic_to_shared(smem);
    asm volatile("cp.async.ca.shared.global [%0], [%1], 16;\n" :: "r"(s), "l"(gmem));
}
__device__ __forceinline__ void cp_commit() { asm volatile("cp.async.commit_group;\n"); }
template<int N> __device__ __forceinline__ void cp_wait() {
    asm volatile("cp.async.wait_group %0;\n" :: "n"(N));
}

// ---------------- tf32 RN weight conversion (all 6 in one launch) -----------
__global__ void tf32_conv_kernel(const float* s0, const float* s1, const float* s2,
                                 const float* s3, const float* s4, const float* s5,
                                 float* __restrict__ dst)
{
    int w = blockIdx.y;
    const float* src = w == 0 ? s0 : w == 1 ? s1 : w == 2 ? s2 : w == 3 ? s3 : w == 4 ? s4 : s5;
    int i = blockIdx.x * blockDim.x + threadIdx.x;   // over float4s
    float4 v = ((const float4*)src)[i];
    v.x = wmma::__float_to_tf32(v.x);
    v.y = wmma::__float_to_tf32(v.y);
    v.z = wmma::__float_to_tf32(v.z);
    v.w = wmma::__float_to_tf32(v.w);
    ((float4*)(dst + (size_t)w * DIM * DIM))[i] = v;
}

// ---------------- LayerNorm (tf32-rounded output) ---------------------------
__global__ void ln_kernel(const float* __restrict__ x, const float* __restrict__ g,
                          const float* __restrict__ b, float* __restrict__ y)
{
    int row = blockIdx.x;
    int t = threadIdx.x;                       // 256 threads, 4 floats each
    const float4* xr = (const float4*)(x + (size_t)row * DIM);
    float4 xv = xr[t];

    float s  = xv.x + xv.y + xv.z + xv.w;
    float sq = xv.x*xv.x + xv.y*xv.y + xv.z*xv.z + xv.w*xv.w;

    __shared__ float red[16];
    #pragma unroll
    for (int o = 16; o; o >>= 1) {
        s  += __shfl_xor_sync(0xffffffffu, s,  o);
        sq += __shfl_xor_sync(0xffffffffu, sq, o);
    }
    int wid = t >> 5, lid = t & 31;
    if (lid == 0) { red[wid] = s; red[8 + wid] = sq; }
    __syncthreads();
    if (t == 0) {
        float S = 0.f, SQ = 0.f;
        #pragma unroll
        for (int i = 0; i < 8; i++) { S += red[i]; SQ += red[8 + i]; }
        red[0] = S; red[8] = SQ;
    }
    __syncthreads();
    float mu  = red[0] * (1.f / DIM);
    float var = red[8] * (1.f / DIM) - mu * mu;
    float inv = rsqrtf(var + 1e-5f);

    float4 gv = ((const float4*)g)[t];
    float4 bv = ((const float4*)b)[t];
    float4 o;
    o.x = wmma::__float_to_tf32((xv.x - mu) * inv * gv.x + bv.x);
    o.y = wmma::__float_to_tf32((xv.y - mu) * inv * gv.y + bv.y);
    o.z = wmma::__float_to_tf32((xv.z - mu) * inv * gv.z + bv.z);
    o.w = wmma::__float_to_tf32((xv.w - mu) * inv * gv.w + bv.w);
    ((float4*)(y + (size_t)row * DIM))[t] = o;
}

// ---------------- Projection GEMM v3 ----------------------------------------
// C = X @ W^T + bias, head-scattered. Block 256x128, BK=32, 8 warps with
// 64x64 warp tiles (2.0 LDS per MMA), cp.async double-buffered, z = q/k/v.
#define PBM 256
#define PBN 128
#define PBK 32
#define PLD 36
#define PASZ (PBM*PLD)
#define PBSZ (PBN*PLD)
#define PSTG (PASZ+PBSZ)
#define PROJ_SMEM (2*PSTG*4)    // 110,592 B

__global__ __launch_bounds__(256, 1) void proj_kernel(
    const float* __restrict__ X, const float* __restrict__ Wbase,
    const float* b0, const float* b1, const float* b2,
    float* o0, float* o1, float* o2, int seqlen)
{
    extern __shared__ float sm[];
    float* Csh = sm;                         // epilogue alias, ld=132

    int z = blockIdx.z;
    const float* W    = Wbase + (size_t)z * DIM * DIM;
    const float* bias = z == 0 ? b0 : z == 1 ? b1 : b2;
    float* out        = z == 0 ? o0 : z == 1 ? o1 : o2;

    int t = threadIdx.x;
    int row0 = blockIdx.y * PBM;
    int col0 = blockIdx.x * PBN;
    int wid = t >> 5;
    int warpM = wid >> 1;                    // 0..3 : 64-row slab
    int warpN = wid & 1;                     // 0..1 : 64-col slab

    wmma::fragment<wmma::accumulator, 16, 16, 8, float> acc[4][4];
    #pragma unroll
    for (int mi = 0; mi < 4; mi++)
        #pragma unroll
        for (int nj = 0; nj < 4; nj++)
            wmma::fill_fragment(acc[mi][nj], 0.0f);

    auto stage = [&](int s, int k0) {
        float* Ad = sm + s * PSTG;
        float* Bd = Ad + PASZ;
        #pragma unroll
        for (int i = 0; i < 8; i++) {
            int f = t + i * 256;             // 0..2047 float4s (A: 256x32)
            int r = f >> 3, c = (f & 7) * 4;
            cp_async16(Ad + r*PLD + c, X + (size_t)(row0 + r)*DIM + k0 + c);
        }
        #pragma unroll
        for (int i = 0; i < 4; i++) {
            int f = t + i * 256;             // 0..1023 float4s (B: 128x32)
            int r = f >> 3, c = (f & 7) * 4;
            cp_async16(Bd + r*PLD + c, W + (size_t)(col0 + r)*DIM + k0 + c);
        }
    };

    stage(0, 0);
    cp_commit();

    #pragma unroll 1
    for (int kt = 0; kt < DIM/PBK; kt++) {
        int buf = kt & 1;
        if (kt + 1 < DIM/PBK) {
            stage(buf ^ 1, (kt + 1) * PBK);
            cp_commit();
            cp_wait<1>();
        } else {
            cp_wait<0>();
        }
        __syncthreads();

        float* A = sm + buf * PSTG;
        float* B = A + PASZ;
        #pragma unroll
        for (int kk = 0; kk < 4; kk++) {
            wmma::fragment<wmma::matrix_a, 16, 16, 8, wmma::precision::tf32, wmma::row_major> a[4];
            wmma::fragment<wmma::matrix_b, 16, 16, 8, wmma::precision::tf32, wmma::col_major> bf[4];
            #pragma unroll
            for (int mi = 0; mi < 4; mi++)
                wmma::load_matrix_sync(a[mi], A + (warpM*64 + mi*16)*PLD + kk*8, PLD);
            #pragma unroll
            for (int nj = 0; nj < 4; nj++)
                wmma::load_matrix_sync(bf[nj], B + (warpN*64 + nj*16)*PLD + kk*8, PLD);
            #pragma unroll
            for (int mi = 0; mi < 4; mi++)
                #pragma unroll
                for (int nj = 0; nj < 4; nj++)
                    wmma::mma_sync(acc[mi][nj], a[mi], bf[nj], acc[mi][nj]);
        }
        __syncthreads();
    }

    // epilogue in two 128-row halves through smem
    #pragma unroll
    for (int half = 0; half < 2; half++) {
        if ((warpM >> 1) == half) {
            #pragma unroll
            for (int mi = 0; mi < 4; mi++)
                #pragma unroll
                for (int nj = 0; nj < 4; nj++)
                    wmma::store_matrix_sync(Csh + ((warpM & 1)*64 + mi*16)*132 + warpN*64 + nj*16,
                                            acc[mi][nj], 132, wmma::mem_row_major);
        }
        __syncthreads();
        #pragma unroll
        for (int i = 0; i < 16; i++) {
            int f = t + i * 256;             // 0..4095 float4s over 128x128
            int r = f >> 5, c = (f & 31) * 4;
            float4 v = *(float4*)(Csh + r*132 + c);
            int jg = col0 + c;
            float4 bb = *(const float4*)(bias + jg);
            v.x = wmma::__float_to_tf32(v.x + bb.x);
            v.y = wmma::__float_to_tf32(v.y + bb.y);
            v.z = wmma::__float_to_tf32(v.z + bb.z);
            v.w = wmma::__float_to_tf32(v.w + bb.w);
            int gr = row0 + half * 128 + r;
            int bidx = gr / seqlen;
            int n = gr - bidx * seqlen;
            int h = jg >> 6;
            int d = jg & 63;
            *(float4*)(out + ((size_t)(bidx * HEADS + h) * seqlen + n) * DK + d) = v;
        }
        __syncthreads();
    }
}

// ---------------- Fused flash cross-attention v3 ----------------------------
// Q tile 128, KV chunks 64 (cp.async double-buffered), 512 threads / 16 warps.
// Warp pair per 16-row slab; each warp handles 32 of the 64 columns.
#define ALD 68
#define OFF_Q   0
#define OFF_K   (128*ALD)
#define OFF_V   (OFF_K + 2*64*ALD)
#define OFF_S   (OFF_V + 2*64*ALD)
#define OFF_O   (OFF_S + 128*ALD)
#define OFF_M   (OFF_O + 128*ALD)
#define OFF_L   (OFF_M + 128)
#define ATT_SMEM ((OFF_L + 128) * 4)

__global__ __launch_bounds__(512, 1) void attn_kernel(
    const float* __restrict__ Qg, const float* __restrict__ Kg,
    const float* __restrict__ Vg, float* __restrict__ out, int nq, int nk)
{
    extern __shared__ float sm[];
    float* Qsh = sm + OFF_Q;
    float* Ksh[2] = { sm + OFF_K, sm + OFF_K + 64*ALD };
    float* Vsh[2] = { sm + OFF_V, sm + OFF_V + 64*ALD };
    float* Ssh = sm + OFF_S;
    float* Osh = sm + OFF_O;
    float* msh = sm + OFF_M;
    float* lsh = sm + OFF_L;

    int t = threadIdx.x;
    int w = t >> 5;                          // 0..15
    int slab = w >> 1;                       // 0..7 : 16 q-rows
    int ch = w & 1;                          // 0..1 : 32 kv-cols / o-cols
    int bh = blockIdx.y;
    int q0 = blockIdx.x * 128;

    const float* Qb = Qg + ((size_t)bh * nq + q0) * DK;
    const float* Kb = Kg + (size_t)bh * nk * DK;
    const float* Vb = Vg + (size_t)bh * nk * DK;

    // prologue: async-load Q tile + KV chunk 0
    #pragma unroll
    for (int i = 0; i < 4; i++) {
        int f = t + i * 512;                 // 0..2047
        int r = f >> 4, c = (f & 15) * 4;
        cp_async16(Qsh + r*ALD + c, Qb + (size_t)r*DK + c);
    }
    #pragma unroll
    for (int i = 0; i < 2; i++) {
        int f = t + i * 512;                 // 0..1023
        int r = f >> 4, c = (f & 15) * 4;
        cp_async16(Ksh[0] + r*ALD + c, Kb + (size_t)r*DK + c);
        cp_async16(Vsh[0] + r*ALD + c, Vb + (size_t)r*DK + c);
    }
    cp_commit();

    // init O / m / l
    #pragma unroll
    for (int i = 0; i < 4; i++) {
        int f = t + i * 512;
        int r = f >> 4, c = (f & 15) * 4;
        *(float4*)(Osh + r*ALD + c) = make_float4(0.f, 0.f, 0.f, 0.f);
    }
    if (t < 128) { msh[t] = -1e30f; lsh[t] = 0.f; }

    int nch = nk >> 6;
    #pragma unroll 1
    for (int c = 0; c < nch; c++) {
        int buf = c & 1;
        if (c + 1 < nch) {
            const float* Kc = Kb + (size_t)(c + 1) * 64 * DK;
            const float* Vc = Vb + (size_t)(c + 1) * 64 * DK;
            float* Kd = Ksh[buf ^ 1];
            float* Vd = Vsh[buf ^ 1];
            #pragma unroll
            for (int i = 0; i < 2; i++) {
                int f = t + i * 512;
                int r = f >> 4, cc = (f & 15) * 4;
                cp_async16(Kd + r*ALD + cc, Kc + (size_t)r*DK + cc);
                cp_async16(Vd + r*ALD + cc, Vc + (size_t)r*DK + cc);
            }
            cp_commit();
            cp_wait<1>();
        } else {
            cp_wait<0>();
        }
        __syncthreads();

        // S = (Q @ K^T) * scale : warp -> 16 rows x 32 cols
        wmma::fragment<wmma::accumulator, 16, 16, 8, float> sacc[2];
        #pragma unroll
        for (int j = 0; j < 2; j++) wmma::fill_fragment(sacc[j], 0.0f);
        #pragma unroll
        for (int kk = 0; kk < 8; kk++) {
            wmma::fragment<wmma::matrix_a, 16, 16, 8, wmma::precision::tf32, wmma::row_major> a;
            wmma::load_matrix_sync(a, Qsh + (slab*16)*ALD + kk*8, ALD);
            #pragma unroll
            for (int j = 0; j < 2; j++) {
                wmma::fragment<wmma::matrix_b, 16, 16, 8, wmma::precision::tf32, wmma::col_major> bf;
                wmma::load_matrix_sync(bf, Ksh[buf] + (ch*32 + j*16)*ALD + kk*8, ALD);
                wmma::mma_sync(sacc[j], a, bf, sacc[j]);
            }
        }
        const float scale = 0.125f;          // 1/sqrt(64)
        #pragma unroll
        for (int j = 0; j < 2; j++) {
            #pragma unroll
            for (int e = 0; e < sacc[j].num_elements; e++) sacc[j].x[e] *= scale;
            wmma::store_matrix_sync(Ssh + (slab*16)*ALD + ch*32 + j*16, sacc[j], ALD, wmma::mem_row_major);
        }
        __syncthreads();

        // online softmax: 4 threads per row, 16 cols each; fused O rescale
        {
            int row = t >> 2, q = t & 3;
            float* Sr = Ssh + row*ALD + q*16;
            float mo = msh[row];
            float mx = mo;
            #pragma unroll
            for (int j = 0; j < 16; j++) mx = fmaxf(mx, Sr[j]);
            mx = fmaxf(mx, __shfl_xor_sync(0xffffffffu, mx, 1));
            mx = fmaxf(mx, __shfl_xor_sync(0xffffffffu, mx, 2));
            float sum = 0.f;
            #pragma unroll
            for (int j = 0; j < 16; j++) {
                float p = __expf(Sr[j] - mx);
                sum += p;
                Sr[j] = wmma::__float_to_tf32(p);
            }
            sum += __shfl_xor_sync(0xffffffffu, sum, 1);
            sum += __shfl_xor_sync(0xffffffffu, sum, 2);
            float alpha = __expf(mo - mx);
            if (q == 0) {
                lsh[row] = lsh[row] * alpha + sum;
                msh[row] = mx;
            }
            float* Or = Osh + row*ALD + q*16;
            #pragma unroll
            for (int j = 0; j < 4; j++) {
                float4 v = *(float4*)(Or + j*4);
                v.x *= alpha; v.y *= alpha; v.z *= alpha; v.w *= alpha;
                *(float4*)(Or + j*4) = v;
            }
        }
        __syncthreads();

        // O += P @ V : warp -> 16 rows x 32 cols
        wmma::fragment<wmma::accumulator, 16, 16, 8, float> oacc[2];
        #pragma unroll
        for (int j = 0; j < 2; j++)
            wmma::load_matrix_sync(oacc[j], Osh + (slab*16)*ALD + ch*32 + j*16, ALD, wmma::mem_row_major);
        #pragma unroll
        for (int kk = 0; kk < 8; kk++) {
            wmma::fragment<wmma::matrix_a, 16, 16, 8, wmma::precision::tf32, wmma::row_major> a;
            wmma::load_matrix_sync(a, Ssh + (slab*16)*ALD + kk*8, ALD);
            #pragma unroll
            for (int j = 0; j < 2; j++) {
                wmma::fragment<wmma::matrix_b, 16, 16, 8, wmma::precision::tf32, wmma::row_major> bf;
                wmma::load_matrix_sync(bf, Vsh[buf] + (kk*8)*ALD + ch*32 + j*16, ALD);
                wmma::mma_sync(oacc[j], a, bf, oacc[j]);
            }
        }
        #pragma unroll
        for (int j = 0; j < 2; j++)
            wmma::store_matrix_sync(Osh + (slab*16)*ALD + ch*32 + j*16, oacc[j], ALD, wmma::mem_row_major);
        __syncthreads();
    }

    // epilogue: normalize + merge heads
    int b = bh >> 4, h = bh & 15;
    float* ob = out + ((size_t)(b * nq) + q0) * DIM + h * DK;
    #pragma unroll
    for (int i = 0; i < 4; i++) {
        int f = t + i * 512;
        int r = f >> 4, cc = (f & 15) * 4;
        float inv = 1.f / lsh[r];
        float4 v = *(float4*)(Osh + r*ALD + cc);
        v.x *= inv; v.y *= inv; v.z *= inv; v.w *= inv;
        *(float4*)(ob + (size_t)r * DIM + cc) = v;
    }
}

// ---------------- host launch ------------------------------------------------
extern "C" void kernel_launch(void* const* d_in, const int* in_sizes, int n_in,
                              void* d_out, int out_size)
{
    (void)in_sizes; (void)n_in; (void)out_size;
    const float* text   = (const float*)d_in[0];
    const float* vision = (const float*)d_in[1];
    const float* n1g = (const float*)d_in[2];
    const float* n1b = (const float*)d_in[3];
    const float* n2g = (const float*)d_in[4];
    const float* n2b = (const float*)d_in[5];
    const float* Wq1 = (const float*)d_in[6];
    const float* bq1 = (const float*)d_in[7];
    const float* Wk1 = (const float*)d_in[8];
    const float* bk1 = (const float*)d_in[9];
    const float* Wv1 = (const float*)d_in[10];
    const float* bv1 = (const float*)d_in[11];
    const float* Wq2 = (const float*)d_in[12];
    const float* bq2 = (const float*)d_in[13];
    const float* Wk2 = (const float*)d_in[14];
    const float* bk2 = (const float*)d_in[15];
    const float* Wv2 = (const float*)d_in[16];
    const float* bv2 = (const float*)d_in[17];
    float* out = (float*)d_out;

    float *tn, *vn, *tq, *tk, *tv, *vq, *vk, *vv, *wc;
    cudaGetSymbolAddress((void**)&tn, g_tn);
    cudaGetSymbolAddress((void**)&vn, g_vn);
    cudaGetSymbolAddress((void**)&tq, g_tq);
    cudaGetSymbolAddress((void**)&tk, g_tk);
    cudaGetSymbolAddress((void**)&tv, g_tv);
    cudaGetSymbolAddress((void**)&vq, g_vq);
    cudaGetSymbolAddress((void**)&vk, g_vk);
    cudaGetSymbolAddress((void**)&vv, g_vv);
    cudaGetSymbolAddress((void**)&wc, g_wc);

    const size_t A1 = (size_t)BATCH * NT * DIM;
    const size_t A2 = (size_t)BATCH * NV * DIM;
    const size_t WSZ = (size_t)DIM * DIM;

    // residual passthrough
    cudaMemcpyAsync(out + A1 + A2,      text,   A1 * sizeof(float), cudaMemcpyDeviceToDevice, 0);
    cudaMemcpyAsync(out + A1 + A2 + A1, vision, A2 * sizeof(float), cudaMemcpyDeviceToDevice, 0);

    // tf32 RN-rounded weights (one launch)
    tf32_conv_kernel<<<dim3(WSZ / (256*4), 6), 256>>>(Wq1, Wk1, Wv1, Wq2, Wk2, Wv2, wc);

    ln_kernel<<<BATCH * NT, 256>>>(text,   n1g, n1b, tn);
    ln_kernel<<<BATCH * NV, 256>>>(vision, n2g, n2b, vn);

    cudaFuncSetAttribute(proj_kernel, cudaFuncAttributeMaxDynamicSharedMemorySize, PROJ_SMEM);
    dim3 gt(DIM / PBN, BATCH * NT / PBM, 3);        // 8 x 16 x 3
    dim3 gv(DIM / PBN, BATCH * NV / PBM, 3);        // 8 x 32 x 3
    proj_kernel<<<gt, 256, PROJ_SMEM>>>(tn, wc,           bq1, bk1, bv1, tq, tk, tv, NT);
    proj_kernel<<<gv, 256, PROJ_SMEM>>>(vn, wc + 3*WSZ,   bq2, bk2, bv2, vq, vk, vv, NV);

    cudaFuncSetAttribute(attn_kernel, cudaFuncAttributeMaxDynamicSharedMemorySize, ATT_SMEM);
    attn_kernel<<<dim3(NT / 128, BH), 512, ATT_SMEM>>>(tq, vk, vv, out,      NT, NV);
    attn_kernel<<<dim3(NV / 128, BH), 512, ATT_SMEM>>>(vq, tk, tv, out + A1, NV, NT);
}

// round 4
// speedup vs baseline: 3.4607x; 1.4094x over previous
#include <cuda_runtime.h>
#include <mma.h>

using namespace nvcuda;

#define DIM    1024
#define HEADS  16
#define DK     64
#define BATCH  8
#define NT     512
#define NV     1024
#define BH     (BATCH*HEADS)

// ---------------- scratch (static device globals; allocation-free) ----------
__device__ float g_tn[BATCH*NT*DIM];
__device__ float g_vn[BATCH*NV*DIM];
__device__ float g_tq[BH*NT*DK];
__device__ float g_tk[BH*NT*DK];
__device__ float g_tv[BH*NT*DK];
__device__ float g_vq[BH*NV*DK];
__device__ float g_vk[BH*NV*DK];
__device__ float g_vv[BH*NV*DK];
__device__ float g_wc[6*DIM*DIM];     // tf32-rounded weights

// ---------------- cp.async helpers -----------------------------------------
__device__ __forceinline__ void cp_async16(void* smem, const void* gmem) {
    unsigned s = (unsigned)__cvta_generic_to_shared(smem);
    asm volatile("cp.async.ca.shared.global [%0], [%1], 16;\n" :: "r"(s), "l"(gmem));
}
__device__ __forceinline__ void cp_commit() { asm volatile("cp.async.commit_group;\n"); }
template<int N> __device__ __forceinline__ void cp_wait() {
    asm volatile("cp.async.wait_group %0;\n" :: "n"(N));
}

// ---------------- raw tf32 mma (documented fragment layout) -----------------
__device__ __forceinline__ void mma_tf32(float* d, const float* a, float b0, float b1) {
    asm volatile(
        "mma.sync.aligned.m16n8k8.row.col.f32.tf32.tf32.f32 "
        "{%0,%1,%2,%3}, {%4,%5,%6,%7}, {%8,%9}, {%0,%1,%2,%3};\n"
        : "+f"(d[0]), "+f"(d[1]), "+f"(d[2]), "+f"(d[3])
        : "r"(__float_as_uint(a[0])), "r"(__float_as_uint(a[1])),
          "r"(__float_as_uint(a[2])), "r"(__float_as_uint(a[3])),
          "r"(__float_as_uint(b0)), "r"(__float_as_uint(b1)));
}

// ---------------- tf32 RN weight conversion (all 6 in one launch) -----------
__global__ void tf32_conv_kernel(const float* s0, const float* s1, const float* s2,
                                 const float* s3, const float* s4, const float* s5,
                                 float* __restrict__ dst)
{
    int w = blockIdx.y;
    const float* src = w == 0 ? s0 : w == 1 ? s1 : w == 2 ? s2 : w == 3 ? s3 : w == 4 ? s4 : s5;
    int i = blockIdx.x * blockDim.x + threadIdx.x;   // over float4s
    float4 v = ((const float4*)src)[i];
    v.x = wmma::__float_to_tf32(v.x);
    v.y = wmma::__float_to_tf32(v.y);
    v.z = wmma::__float_to_tf32(v.z);
    v.w = wmma::__float_to_tf32(v.w);
    ((float4*)(dst + (size_t)w * DIM * DIM))[i] = v;
}

// ---------------- LayerNorm (tf32-rounded output) ---------------------------
__global__ void ln_kernel(const float* __restrict__ x, const float* __restrict__ g,
                          const float* __restrict__ b, float* __restrict__ y)
{
    int row = blockIdx.x;
    int t = threadIdx.x;                       // 256 threads, 4 floats each
    const float4* xr = (const float4*)(x + (size_t)row * DIM);
    float4 xv = xr[t];

    float s  = xv.x + xv.y + xv.z + xv.w;
    float sq = xv.x*xv.x + xv.y*xv.y + xv.z*xv.z + xv.w*xv.w;

    __shared__ float red[16];
    #pragma unroll
    for (int o = 16; o; o >>= 1) {
        s  += __shfl_xor_sync(0xffffffffu, s,  o);
        sq += __shfl_xor_sync(0xffffffffu, sq, o);
    }
    int wid = t >> 5, lid = t & 31;
    if (lid == 0) { red[wid] = s; red[8 + wid] = sq; }
    __syncthreads();
    if (t == 0) {
        float S = 0.f, SQ = 0.f;
        #pragma unroll
        for (int i = 0; i < 8; i++) { S += red[i]; SQ += red[8 + i]; }
        red[0] = S; red[8] = SQ;
    }
    __syncthreads();
    float mu  = red[0] * (1.f / DIM);
    float var = red[8] * (1.f / DIM) - mu * mu;
    float inv = rsqrtf(var + 1e-5f);

    float4 gv = ((const float4*)g)[t];
    float4 bv = ((const float4*)b)[t];
    float4 o;
    o.x = wmma::__float_to_tf32((xv.x - mu) * inv * gv.x + bv.x);
    o.y = wmma::__float_to_tf32((xv.y - mu) * inv * gv.y + bv.y);
    o.z = wmma::__float_to_tf32((xv.z - mu) * inv * gv.z + bv.z);
    o.w = wmma::__float_to_tf32((xv.w - mu) * inv * gv.w + bv.w);
    ((float4*)(y + (size_t)row * DIM))[t] = o;
}

// ---------------- Projection GEMM v3 (unchanged from R3) --------------------
#define PBM 256
#define PBN 128
#define PBK 32
#define PLD 36
#define PASZ (PBM*PLD)
#define PBSZ (PBN*PLD)
#define PSTG (PASZ+PBSZ)
#define PROJ_SMEM (2*PSTG*4)

__global__ __launch_bounds__(256, 1) void proj_kernel(
    const float* __restrict__ X, const float* __restrict__ Wbase,
    const float* b0, const float* b1, const float* b2,
    float* o0, float* o1, float* o2, int seqlen)
{
    extern __shared__ float sm[];
    float* Csh = sm;

    int z = blockIdx.z;
    const float* W    = Wbase + (size_t)z * DIM * DIM;
    const float* bias = z == 0 ? b0 : z == 1 ? b1 : b2;
    float* out        = z == 0 ? o0 : z == 1 ? o1 : o2;

    int t = threadIdx.x;
    int row0 = blockIdx.y * PBM;
    int col0 = blockIdx.x * PBN;
    int wid = t >> 5;
    int warpM = wid >> 1;
    int warpN = wid & 1;

    wmma::fragment<wmma::accumulator, 16, 16, 8, float> acc[4][4];
    #pragma unroll
    for (int mi = 0; mi < 4; mi++)
        #pragma unroll
        for (int nj = 0; nj < 4; nj++)
            wmma::fill_fragment(acc[mi][nj], 0.0f);

    auto stage = [&](int s, int k0) {
        float* Ad = sm + s * PSTG;
        float* Bd = Ad + PASZ;
        #pragma unroll
        for (int i = 0; i < 8; i++) {
            int f = t + i * 256;
            int r = f >> 3, c = (f & 7) * 4;
            cp_async16(Ad + r*PLD + c, X + (size_t)(row0 + r)*DIM + k0 + c);
        }
        #pragma unroll
        for (int i = 0; i < 4; i++) {
            int f = t + i * 256;
            int r = f >> 3, c = (f & 7) * 4;
            cp_async16(Bd + r*PLD + c, W + (size_t)(col0 + r)*DIM + k0 + c);
        }
    };

    stage(0, 0);
    cp_commit();

    #pragma unroll 1
    for (int kt = 0; kt < DIM/PBK; kt++) {
        int buf = kt & 1;
        if (kt + 1 < DIM/PBK) {
            stage(buf ^ 1, (kt + 1) * PBK);
            cp_commit();
            cp_wait<1>();
        } else {
            cp_wait<0>();
        }
        __syncthreads();

        float* A = sm + buf * PSTG;
        float* B = A + PASZ;
        #pragma unroll
        for (int kk = 0; kk < 4; kk++) {
            wmma::fragment<wmma::matrix_a, 16, 16, 8, wmma::precision::tf32, wmma::row_major> a[4];
            wmma::fragment<wmma::matrix_b, 16, 16, 8, wmma::precision::tf32, wmma::col_major> bf[4];
            #pragma unroll
            for (int mi = 0; mi < 4; mi++)
                wmma::load_matrix_sync(a[mi], A + (warpM*64 + mi*16)*PLD + kk*8, PLD);
            #pragma unroll
            for (int nj = 0; nj < 4; nj++)
                wmma::load_matrix_sync(bf[nj], B + (warpN*64 + nj*16)*PLD + kk*8, PLD);
            #pragma unroll
            for (int mi = 0; mi < 4; mi++)
                #pragma unroll
                for (int nj = 0; nj < 4; nj++)
                    wmma::mma_sync(acc[mi][nj], a[mi], bf[nj], acc[mi][nj]);
        }
        __syncthreads();
    }

    #pragma unroll
    for (int half = 0; half < 2; half++) {
        if ((warpM >> 1) == half) {
            #pragma unroll
            for (int mi = 0; mi < 4; mi++)
                #pragma unroll
                for (int nj = 0; nj < 4; nj++)
                    wmma::store_matrix_sync(Csh + ((warpM & 1)*64 + mi*16)*132 + warpN*64 + nj*16,
                                            acc[mi][nj], 132, wmma::mem_row_major);
        }
        __syncthreads();
        #pragma unroll
        for (int i = 0; i < 16; i++) {
            int f = t + i * 256;
            int r = f >> 5, c = (f & 31) * 4;
            float4 v = *(float4*)(Csh + r*132 + c);
            int jg = col0 + c;
            float4 bb = *(const float4*)(bias + jg);
            v.x = wmma::__float_to_tf32(v.x + bb.x);
            v.y = wmma::__float_to_tf32(v.y + bb.y);
            v.z = wmma::__float_to_tf32(v.z + bb.z);
            v.w = wmma::__float_to_tf32(v.w + bb.w);
            int gr = row0 + half * 128 + r;
            int bidx = gr / seqlen;
            int n = gr - bidx * seqlen;
            int h = jg >> 6;
            int d = jg & 63;
            *(float4*)(out + ((size_t)(bidx * HEADS + h) * seqlen + n) * DK + d) = v;
        }
        __syncthreads();
    }
}

// ---------------- Flash cross-attention v4: register-resident mma.sync ------
// 256 threads / 8 warps; warp owns 16 q-rows x full dk=64. Q tile 128 rows.
// S and O live in registers; softmax in registers via quad shuffles; smem only
// for Q (once) and double-buffered K/V chunks of 64.
#define QLD 68
#define KLD 68
#define VLD 72
#define AQ_SZ  (128*QLD)
#define AK_SZ  (64*KLD)
#define AV_SZ  (64*VLD)
#define ATT_SMEM ((AQ_SZ + 2*AK_SZ + 2*AV_SZ) * 4)   // 106,496 B

__global__ __launch_bounds__(256, 1) void attn_kernel(
    const float* __restrict__ Qg, const float* __restrict__ Kg,
    const float* __restrict__ Vg, float* __restrict__ out, int nq, int nk)
{
    extern __shared__ float sm[];
    float* Qsh  = sm;
    float* Ksh0 = sm + AQ_SZ;
    float* Vsh0 = Ksh0 + 2*AK_SZ;

    int t = threadIdx.x;
    int w = t >> 5;
    int lane = t & 31;
    int g = lane >> 2;            // row group 0..7
    int tig = lane & 3;           // thread-in-group
    int bh = blockIdx.y;
    int q0 = blockIdx.x * 128;

    const float* Qb = Qg + ((size_t)bh * nq + q0) * DK;
    const float* Kb = Kg + (size_t)bh * nk * DK;
    const float* Vb = Vg + (size_t)bh * nk * DK;

    // stage Q (128x64) + KV chunk 0 (64x64 each)
    #pragma unroll
    for (int i = 0; i < 8; i++) {
        int f = t + i * 256;                 // 0..2047 float4s
        int r = f >> 4, c = (f & 15) * 4;
        cp_async16(Qsh + r*QLD + c, Qb + (size_t)r*DK + c);
    }
    #pragma unroll
    for (int i = 0; i < 4; i++) {
        int f = t + i * 256;                 // 0..1023
        int r = f >> 4, c = (f & 15) * 4;
        cp_async16(Ksh0 + r*KLD + c, Kb + (size_t)r*DK + c);
        cp_async16(Vsh0 + r*VLD + c, Vb + (size_t)r*DK + c);
    }
    cp_commit();
    cp_wait<0>();
    __syncthreads();

    // Q fragments (A operand, scale 1/8 folded in — exact power of two)
    float qa[8][4];
    {
        const float* q0p = Qsh + (w*16 + g) * QLD;       // row g
        const float* q1p = Qsh + (w*16 + g + 8) * QLD;   // row g+8
        #pragma unroll
        for (int j = 0; j < 8; j++) {
            qa[j][0] = q0p[8*j + tig]     * 0.125f;
            qa[j][1] = q1p[8*j + tig]     * 0.125f;
            qa[j][2] = q0p[8*j + tig + 4] * 0.125f;
            qa[j][3] = q1p[8*j + tig + 4] * 0.125f;
        }
    }

    float o[8][4];
    #pragma unroll
    for (int n = 0; n < 8; n++)
        #pragma unroll
        for (int e = 0; e < 4; e++) o[n][e] = 0.f;
    float m0 = -1e30f, m1 = -1e30f, l0 = 0.f, l1 = 0.f;

    int base = lane & ~3;
    int nch = nk >> 6;

    #pragma unroll 1
    for (int c = 0; c < nch; c++) {
        int buf = c & 1;
        // prefetch next chunk into buf^1 (that buffer was released by the
        // __syncthreads at the end of the previous iteration)
        if (c + 1 < nch) {
            const float* Kc = Kb + (size_t)(c + 1) * 64 * DK;
            const float* Vc = Vb + (size_t)(c + 1) * 64 * DK;
            float* Kd = Ksh0 + (buf ^ 1) * AK_SZ;
            float* Vd = Vsh0 + (buf ^ 1) * AV_SZ;
            #pragma unroll
            for (int i = 0; i < 4; i++) {
                int f = t + i * 256;
                int r = f >> 4, cc = (f & 15) * 4;
                cp_async16(Kd + r*KLD + cc, Kc + (size_t)r*DK + cc);
                cp_async16(Vd + r*VLD + cc, Vc + (size_t)r*DK + cc);
            }
            cp_commit();
            cp_wait<1>();
        } else {
            cp_wait<0>();
        }
        __syncthreads();

        const float* K = Ksh0 + buf * AK_SZ;
        const float* V = Vsh0 + buf * AV_SZ;

        // ---- S = Q @ K^T (scaled) : 8 n-tiles x 8 k-steps -------------------
        float s[8][4];
        #pragma unroll
        for (int n = 0; n < 8; n++) {
            s[n][0] = 0.f; s[n][1] = 0.f; s[n][2] = 0.f; s[n][3] = 0.f;
            const float* Kn = K + (8*n + g) * KLD;
            #pragma unroll
            for (int j = 0; j < 8; j++) {
                float b0 = Kn[8*j + tig];
                float b1 = Kn[8*j + tig + 4];
                mma_tf32(s[n], qa[j], b0, b1);
            }
        }

        // ---- online softmax in registers -----------------------------------
        float mx0 = m0, mx1 = m1;
        #pragma unroll
        for (int n = 0; n < 8; n++) {
            mx0 = fmaxf(mx0, fmaxf(s[n][0], s[n][1]));
            mx1 = fmaxf(mx1, fmaxf(s[n][2], s[n][3]));
        }
        mx0 = fmaxf(mx0, __shfl_xor_sync(0xffffffffu, mx0, 1));
        mx0 = fmaxf(mx0, __shfl_xor_sync(0xffffffffu, mx0, 2));
        mx1 = fmaxf(mx1, __shfl_xor_sync(0xffffffffu, mx1, 1));
        mx1 = fmaxf(mx1, __shfl_xor_sync(0xffffffffu, mx1, 2));
        float alpha0 = __expf(m0 - mx0);
        float alpha1 = __expf(m1 - mx1);
        m0 = mx0; m1 = mx1;

        float sum0 = 0.f, sum1 = 0.f;
        #pragma unroll
        for (int n = 0; n < 8; n++) {
            float p0 = __expf(s[n][0] - mx0);
            float p1 = __expf(s[n][1] - mx0);
            float p2 = __expf(s[n][2] - mx1);
            float p3 = __expf(s[n][3] - mx1);
            sum0 += p0 + p1; sum1 += p2 + p3;
            s[n][0] = wmma::__float_to_tf32(p0);
            s[n][1] = wmma::__float_to_tf32(p1);
            s[n][2] = wmma::__float_to_tf32(p2);
            s[n][3] = wmma::__float_to_tf32(p3);
        }
        sum0 += __shfl_xor_sync(0xffffffffu, sum0, 1);
        sum0 += __shfl_xor_sync(0xffffffffu, sum0, 2);
        sum1 += __shfl_xor_sync(0xffffffffu, sum1, 1);
        sum1 += __shfl_xor_sync(0xffffffffu, sum1, 2);
        l0 = l0 * alpha0 + sum0;
        l1 = l1 * alpha1 + sum1;

        #pragma unroll
        for (int n = 0; n < 8; n++) {
            o[n][0] *= alpha0; o[n][1] *= alpha0;
            o[n][2] *= alpha1; o[n][3] *= alpha1;
        }

        // ---- O += P @ V -----------------------------------------------------
        // permute C-layout P (cols {2t,2t+1}) -> A-layout (cols {t,t+4}) via quad shuffles
        #pragma unroll
        for (int j = 0; j < 8; j++) {
            int src = base + (tig >> 1);
            float e0 = __shfl_sync(0xffffffffu, s[j][0], src);
            float d0 = __shfl_sync(0xffffffffu, s[j][1], src);
            float e2 = __shfl_sync(0xffffffffu, s[j][0], src + 2);
            float d2 = __shfl_sync(0xffffffffu, s[j][1], src + 2);
            float e1 = __shfl_sync(0xffffffffu, s[j][2], src);
            float d1 = __shfl_sync(0xffffffffu, s[j][3], src);
            float e3 = __shfl_sync(0xffffffffu, s[j][2], src + 2);
            float d3 = __shfl_sync(0xffffffffu, s[j][3], src + 2);
            float pa[4];
            bool odd = (tig & 1);
            pa[0] = odd ? d0 : e0;
            pa[1] = odd ? d1 : e1;
            pa[2] = odd ? d2 : e2;
            pa[3] = odd ? d3 : e3;
            const float* Vj = V + (8*j + tig) * VLD;
            const float* Vj4 = V + (8*j + tig + 4) * VLD;
            #pragma unroll
            for (int n = 0; n < 8; n++) {
                float b0 = Vj[8*n + g];
                float b1 = Vj4[8*n + g];
                mma_tf32(o[n], pa, b0, b1);
            }
        }
        __syncthreads();   // all warps done with buf before next prefetch overwrites buf^1
    }

    // ---- epilogue: normalize + merge heads (direct from registers) ---------
    float inv0 = 1.f / l0;
    float inv1 = 1.f / l1;
    int b = bh >> 4, h = bh & 15;
    float* ob = out + ((size_t)(b * nq) + q0 + w*16) * DIM + h * DK;
    #pragma unroll
    for (int n = 0; n < 8; n++) {
        float2 v0 = make_float2(o[n][0] * inv0, o[n][1] * inv0);
        float2 v1 = make_float2(o[n][2] * inv1, o[n][3] * inv1);
        *(float2*)(ob + (size_t)g * DIM + 8*n + 2*tig) = v0;
        *(float2*)(ob + (size_t)(g + 8) * DIM + 8*n + 2*tig) = v1;
    }
}

// ---------------- host launch ------------------------------------------------
extern "C" void kernel_launch(void* const* d_in, const int* in_sizes, int n_in,
                              void* d_out, int out_size)
{
    (void)in_sizes; (void)n_in; (void)out_size;
    const float* text   = (const float*)d_in[0];
    const float* vision = (const float*)d_in[1];
    const float* n1g = (const float*)d_in[2];
    const float* n1b = (const float*)d_in[3];
    const float* n2g = (const float*)d_in[4];
    const float* n2b = (const float*)d_in[5];
    const float* Wq1 = (const float*)d_in[6];
    const float* bq1 = (const float*)d_in[7];
    const float* Wk1 = (const float*)d_in[8];
    const float* bk1 = (const float*)d_in[9];
    const float* Wv1 = (const float*)d_in[10];
    const float* bv1 = (const float*)d_in[11];
    const float* Wq2 = (const float*)d_in[12];
    const float* bq2 = (const float*)d_in[13];
    const float* Wk2 = (const float*)d_in[14];
    const float* bk2 = (const float*)d_in[15];
    const float* Wv2 = (const float*)d_in[16];
    const float* bv2 = (const float*)d_in[17];
    float* out = (float*)d_out;

    float *tn, *vn, *tq, *tk, *tv, *vq, *vk, *vv, *wc;
    cudaGetSymbolAddress((void**)&tn, g_tn);
    cudaGetSymbolAddress((void**)&vn, g_vn);
    cudaGetSymbolAddress((void**)&tq, g_tq);
    cudaGetSymbolAddress((void**)&tk, g_tk);
    cudaGetSymbolAddress((void**)&tv, g_tv);
    cudaGetSymbolAddress((void**)&vq, g_vq);
    cudaGetSymbolAddress((void**)&vk, g_vk);
    cudaGetSymbolAddress((void**)&vv, g_vv);
    cudaGetSymbolAddress((void**)&wc, g_wc);

    const size_t A1 = (size_t)BATCH * NT * DIM;
    const size_t A2 = (size_t)BATCH * NV * DIM;
    const size_t WSZ = (size_t)DIM * DIM;

    // residual passthrough
    cudaMemcpyAsync(out + A1 + A2,      text,   A1 * sizeof(float), cudaMemcpyDeviceToDevice, 0);
    cudaMemcpyAsync(out + A1 + A2 + A1, vision, A2 * sizeof(float), cudaMemcpyDeviceToDevice, 0);

    // tf32 RN-rounded weights (one launch)
    tf32_conv_kernel<<<dim3(WSZ / (256*4), 6), 256>>>(Wq1, Wk1, Wv1, Wq2, Wk2, Wv2, wc);

    ln_kernel<<<BATCH * NT, 256>>>(text,   n1g, n1b, tn);
    ln_kernel<<<BATCH * NV, 256>>>(vision, n2g, n2b, vn);

    cudaFuncSetAttribute(proj_kernel, cudaFuncAttributeMaxDynamicSharedMemorySize, PROJ_SMEM);
    dim3 gt(DIM / PBN, BATCH * NT / PBM, 3);
    dim3 gv(DIM / PBN, BATCH * NV / PBM, 3);
    proj_kernel<<<gt, 256, PROJ_SMEM>>>(tn, wc,           bq1, bk1, bv1, tq, tk, tv, NT);
    proj_kernel<<<gv, 256, PROJ_SMEM>>>(vn, wc + 3*WSZ,   bq2, bk2, bv2, vq, vk, vv, NV);

    cudaFuncSetAttribute(attn_kernel, cudaFuncAttributeMaxDynamicSharedMemorySize, ATT_SMEM);
    attn_kernel<<<dim3(NT / 128, BH), 256, ATT_SMEM>>>(tq, vk, vv, out,      NT, NV);
    attn_kernel<<<dim3(NV / 128, BH), 256, ATT_SMEM>>>(vq, tk, tv, out + A1, NV, NT);
}

// round 5
// speedup vs baseline: 8.5375x; 2.4670x over previous
#include <cuda_runtime.h>
#include <cuda_fp16.h>
#include <mma.h>

using namespace nvcuda;

#define DIM    1024
#define HEADS  16
#define DK     64
#define BATCH  8
#define NT     512
#define NV     1024
#define BH     (BATCH*HEADS)

// ---------------- scratch (static device globals; allocation-free) ----------
__device__ __half g_tn[BATCH*NT*DIM];
__device__ __half g_vn[BATCH*NV*DIM];
__device__ __half g_tq[BH*NT*DK];
__device__ __half g_tk[BH*NT*DK];
__device__ __half g_tv[BH*NT*DK];   // TRANSPOSED: [bh][d][seq]
__device__ __half g_vq[BH*NV*DK];
__device__ __half g_vk[BH*NV*DK];
__device__ __half g_vv[BH*NV*DK];   // TRANSPOSED: [bh][d][seq]
__device__ __half g_wc[6*DIM*DIM];  // fp16 weights

// ---------------- cp.async helpers -----------------------------------------
__device__ __forceinline__ void cp_async16(void* smem, const void* gmem) {
    unsigned s = (unsigned)__cvta_generic_to_shared(smem);
    asm volatile("cp.async.ca.shared.global [%0], [%1], 16;\n" :: "r"(s), "l"(gmem));
}
__device__ __forceinline__ void cp_commit() { asm volatile("cp.async.commit_group;\n"); }
template<int N> __device__ __forceinline__ void cp_wait() {
    asm volatile("cp.async.wait_group %0;\n" :: "n"(N));
}

// ---------------- raw fp16 mma m16n8k16 (documented layout) -----------------
__device__ __forceinline__ void mma_f16(float* d, const unsigned* a, unsigned b0, unsigned b1) {
    asm volatile(
        "mma.sync.aligned.m16n8k16.row.col.f32.f16.f16.f32 "
        "{%0,%1,%2,%3}, {%4,%5,%6,%7}, {%8,%9}, {%0,%1,%2,%3};\n"
        : "+f"(d[0]), "+f"(d[1]), "+f"(d[2]), "+f"(d[3])
        : "r"(a[0]), "r"(a[1]), "r"(a[2]), "r"(a[3]), "r"(b0), "r"(b1));
}

__device__ __forceinline__ unsigned packh2(float lo, float hi) {
    __half2 h = __floats2half2_rn(lo, hi);
    return *(unsigned*)&h;
}

// ---------------- fp32 -> fp16 weight conversion (all 6, one launch) --------
__global__ void half_conv_kernel(const float* s0, const float* s1, const float* s2,
                                 const float* s3, const float* s4, const float* s5,
                                 __half* __restrict__ dst)
{
    int w = blockIdx.y;
    const float* src = w == 0 ? s0 : w == 1 ? s1 : w == 2 ? s2 : w == 3 ? s3 : w == 4 ? s4 : s5;
    int i = blockIdx.x * blockDim.x + threadIdx.x;   // over float4s
    float4 v = ((const float4*)src)[i];
    uint2 o;
    o.x = packh2(v.x, v.y);
    o.y = packh2(v.z, v.w);
    ((uint2*)(dst + (size_t)w * DIM * DIM))[i] = o;
}

// ---------------- LayerNorm (fp16 output) -----------------------------------
__global__ void ln_kernel(const float* __restrict__ x, const float* __restrict__ g,
                          const float* __restrict__ b, __half* __restrict__ y)
{
    int row = blockIdx.x;
    int t = threadIdx.x;                       // 256 threads, 4 floats each
    const float4* xr = (const float4*)(x + (size_t)row * DIM);
    float4 xv = xr[t];

    float s  = xv.x + xv.y + xv.z + xv.w;
    float sq = xv.x*xv.x + xv.y*xv.y + xv.z*xv.z + xv.w*xv.w;

    __shared__ float red[16];
    #pragma unroll
    for (int o = 16; o; o >>= 1) {
        s  += __shfl_xor_sync(0xffffffffu, s,  o);
        sq += __shfl_xor_sync(0xffffffffu, sq, o);
    }
    int wid = t >> 5, lid = t & 31;
    if (lid == 0) { red[wid] = s; red[8 + wid] = sq; }
    __syncthreads();
    if (t == 0) {
        float S = 0.f, SQ = 0.f;
        #pragma unroll
        for (int i = 0; i < 8; i++) { S += red[i]; SQ += red[8 + i]; }
        red[0] = S; red[8] = SQ;
    }
    __syncthreads();
    float mu  = red[0] * (1.f / DIM);
    float var = red[8] * (1.f / DIM) - mu * mu;
    float inv = rsqrtf(var + 1e-5f);

    float4 gv = ((const float4*)g)[t];
    float4 bv = ((const float4*)b)[t];
    uint2 o;
    o.x = packh2((xv.x - mu) * inv * gv.x + bv.x, (xv.y - mu) * inv * gv.y + bv.y);
    o.y = packh2((xv.z - mu) * inv * gv.z + bv.z, (xv.w - mu) * inv * gv.w + bv.w);
    ((uint2*)(y + (size_t)row * DIM))[t] = o;
}

// ---------------- Projection GEMM v4 (fp16 wmma) -----------------------------
// C = X @ W^T + bias. Block 256x128, BK=64, 8 warps, 64x64 warp tiles.
// z selects q/k/v; v output is stored TRANSPOSED [bh][d][seq] for attention.
#define PBM 256
#define PBN 128
#define PBK 64
#define PLDH 72
#define PASZ (PBM*PLDH)
#define PBSZ (PBN*PLDH)
#define PSTG (PASZ+PBSZ)
#define PROJ_SMEM (2*PSTG*2)     // 110,592 B (halfs) ; Csh alias 67,584 B fits

__global__ __launch_bounds__(256, 1) void proj_kernel(
    const __half* __restrict__ X, const __half* __restrict__ Wbase,
    const float* b0, const float* b1, const float* b2,
    __half* o0, __half* o1, __half* o2, int seqlen)
{
    extern __shared__ char smraw[];
    __half* sm = (__half*)smraw;
    float* Csh = (float*)smraw;              // epilogue alias, ld=132

    int z = blockIdx.z;
    const __half* W   = Wbase + (size_t)z * DIM * DIM;
    const float* bias = z == 0 ? b0 : z == 1 ? b1 : b2;
    __half* out       = z == 0 ? o0 : z == 1 ? o1 : o2;

    int t = threadIdx.x;
    int row0 = blockIdx.y * PBM;
    int col0 = blockIdx.x * PBN;
    int wid = t >> 5;
    int warpM = wid >> 1;                    // 0..3 : 64-row slab
    int warpN = wid & 1;                     // 0..1 : 64-col slab

    wmma::fragment<wmma::accumulator, 16, 16, 16, float> acc[4][4];
    #pragma unroll
    for (int mi = 0; mi < 4; mi++)
        #pragma unroll
        for (int nj = 0; nj < 4; nj++)
            wmma::fill_fragment(acc[mi][nj], 0.0f);

    auto stage = [&](int s, int k0) {
        __half* Ad = sm + s * PSTG;
        __half* Bd = Ad + PASZ;
        #pragma unroll
        for (int i = 0; i < 8; i++) {
            int f = t + i * 256;             // 0..2047 chunks (A: 256 rows x 8)
            int r = f >> 3, c = (f & 7) * 8;
            cp_async16(Ad + r*PLDH + c, X + (size_t)(row0 + r)*DIM + k0 + c);
        }
        #pragma unroll
        for (int i = 0; i < 4; i++) {
            int f = t + i * 256;             // 0..1023 chunks (B: 128 rows x 8)
            int r = f >> 3, c = (f & 7) * 8;
            cp_async16(Bd + r*PLDH + c, W + (size_t)(col0 + r)*DIM + k0 + c);
        }
    };

    stage(0, 0);
    cp_commit();

    #pragma unroll 1
    for (int kt = 0; kt < DIM/PBK; kt++) {
        int buf = kt & 1;
        if (kt + 1 < DIM/PBK) {
            stage(buf ^ 1, (kt + 1) * PBK);
            cp_commit();
            cp_wait<1>();
        } else {
            cp_wait<0>();
        }
        __syncthreads();

        __half* A = sm + buf * PSTG;
        __half* B = A + PASZ;
        #pragma unroll
        for (int kk = 0; kk < 4; kk++) {
            wmma::fragment<wmma::matrix_a, 16, 16, 16, __half, wmma::row_major> a[4];
            wmma::fragment<wmma::matrix_b, 16, 16, 16, __half, wmma::col_major> bf[4];
            #pragma unroll
            for (int mi = 0; mi < 4; mi++)
                wmma::load_matrix_sync(a[mi], A + (warpM*64 + mi*16)*PLDH + kk*16, PLDH);
            #pragma unroll
            for (int nj = 0; nj < 4; nj++)
                wmma::load_matrix_sync(bf[nj], B + (warpN*64 + nj*16)*PLDH + kk*16, PLDH);
            #pragma unroll
            for (int mi = 0; mi < 4; mi++)
                #pragma unroll
                for (int nj = 0; nj < 4; nj++)
                    wmma::mma_sync(acc[mi][nj], a[mi], bf[nj], acc[mi][nj]);
        }
        __syncthreads();
    }

    // epilogue in two 128-row halves through smem (fp32), then bias + fp16 store
    #pragma unroll
    for (int half_ = 0; half_ < 2; half_++) {
        if ((warpM >> 1) == half_) {
            #pragma unroll
            for (int mi = 0; mi < 4; mi++)
                #pragma unroll
                for (int nj = 0; nj < 4; nj++)
                    wmma::store_matrix_sync(Csh + ((warpM & 1)*64 + mi*16)*132 + warpN*64 + nj*16,
                                            acc[mi][nj], 132, wmma::mem_row_major);
        }
        __syncthreads();
        #pragma unroll
        for (int i = 0; i < 16; i++) {
            int f = t + i * 256;             // 0..4095 float4s over 128x128
            int r = f >> 5, c = (f & 31) * 4;
            float4 v = *(float4*)(Csh + r*132 + c);
            int jg = col0 + c;
            float4 bb = *(const float4*)(bias + jg);
            v.x += bb.x; v.y += bb.y; v.z += bb.z; v.w += bb.w;
            int gr = row0 + half_ * 128 + r;
            int bidx = gr / seqlen;
            int n = gr - bidx * seqlen;
            int h = jg >> 6;
            int d = jg & 63;
            int bh = bidx * HEADS + h;
            if (z < 2) {
                uint2 o;
                o.x = packh2(v.x, v.y);
                o.y = packh2(v.z, v.w);
                *(uint2*)(out + ((size_t)bh * seqlen + n) * DK + d) = o;
            } else {
                // transposed V: [bh][d][seq]
                __half* vt = out + ((size_t)bh * DK + d) * seqlen + n;
                vt[0]          = __float2half_rn(v.x);
                vt[seqlen]     = __float2half_rn(v.y);
                vt[2*seqlen]   = __float2half_rn(v.z);
                vt[3*seqlen]   = __float2half_rn(v.w);
            }
        }
        __syncthreads();
    }
}

// ---------------- Flash cross-attention v5: fp16 mma, register-resident ------
// 256 threads / 8 warps; warp owns 16 q-rows x dk=64. Q tile 128 rows.
// P C-fragments feed PV A-fragments directly (no shuffles). V pre-transposed.
#define QLDH 72
#define KLDH 72
#define VLDH 72
#define AQ_SZ  (128*QLDH)
#define AK_SZ  (64*KLDH)
#define AV_SZ  (64*VLDH)
#define ATT_SMEM ((AQ_SZ + 2*AK_SZ + 2*AV_SZ) * 2)   // 55,296 B

__global__ __launch_bounds__(256, 2) void attn_kernel(
    const __half* __restrict__ Qg, const __half* __restrict__ Kg,
    const __half* __restrict__ Vtg, float* __restrict__ out, int nq, int nk)
{
    extern __shared__ char smraw[];
    __half* smh  = (__half*)smraw;
    __half* Qsh  = smh;
    __half* Ksh0 = smh + AQ_SZ;
    __half* Vsh0 = Ksh0 + 2*AK_SZ;

    int t = threadIdx.x;
    int w = t >> 5;
    int lane = t & 31;
    int g = lane >> 2;            // row group 0..7
    int tig = lane & 3;           // thread-in-group
    int bh = blockIdx.y;
    int q0 = blockIdx.x * 128;

    const __half* Qb  = Qg  + ((size_t)bh * nq + q0) * DK;
    const __half* Kb  = Kg  + (size_t)bh * nk * DK;
    const __half* Vtb = Vtg + (size_t)bh * DK * nk;   // [d][kv]

    // stage Q (128x64) + K chunk 0 (64x64) + Vt chunk 0 (64 d-rows x 64 kv)
    #pragma unroll
    for (int i = 0; i < 4; i++) {
        int f = t + i * 256;                 // 0..1023 16B-chunks
        int r = f >> 3, c = (f & 7) * 8;
        cp_async16(Qsh + r*QLDH + c, Qb + (size_t)r*DK + c);
    }
    #pragma unroll
    for (int i = 0; i < 2; i++) {
        int f = t + i * 256;                 // 0..511
        int r = f >> 3, c = (f & 7) * 8;
        cp_async16(Ksh0 + r*KLDH + c, Kb + (size_t)r*DK + c);
        cp_async16(Vsh0 + r*VLDH + c, Vtb + (size_t)r*nk + c);
    }
    cp_commit();
    cp_wait<0>();
    __syncthreads();

    // Q fragments: 4 k-blocks of 16; scale 1/8 folded in (exact in fp16)
    unsigned qa[4][4];
    {
        const __half2 sc = __float2half2_rn(0.125f);
        const __half* q0p = Qsh + (w*16 + g) * QLDH;
        const __half* q1p = Qsh + (w*16 + g + 8) * QLDH;
        #pragma unroll
        for (int j = 0; j < 4; j++) {
            __half2 a0 = __hmul2(*(const __half2*)(q0p + 16*j + 2*tig), sc);
            __half2 a1 = __hmul2(*(const __half2*)(q1p + 16*j + 2*tig), sc);
            __half2 a2 = __hmul2(*(const __half2*)(q0p + 16*j + 8 + 2*tig), sc);
            __half2 a3 = __hmul2(*(const __half2*)(q1p + 16*j + 8 + 2*tig), sc);
            qa[j][0] = *(unsigned*)&a0;
            qa[j][1] = *(unsigned*)&a1;
            qa[j][2] = *(unsigned*)&a2;
            qa[j][3] = *(unsigned*)&a3;
        }
    }

    float o[8][4];
    #pragma unroll
    for (int n = 0; n < 8; n++)
        #pragma unroll
        for (int e = 0; e < 4; e++) o[n][e] = 0.f;
    float m0 = -1e30f, m1 = -1e30f, l0 = 0.f, l1 = 0.f;

    int nch = nk >> 6;
    #pragma unroll 1
    for (int c = 0; c < nch; c++) {
        int buf = c & 1;
        if (c + 1 < nch) {
            const __half* Kc  = Kb  + (size_t)(c + 1) * 64 * DK;
            const __half* Vtc = Vtb + (size_t)(c + 1) * 64;      // col offset in [d][kv]
            __half* Kd = Ksh0 + (buf ^ 1) * AK_SZ;
            __half* Vd = Vsh0 + (buf ^ 1) * AV_SZ;
            #pragma unroll
            for (int i = 0; i < 2; i++) {
                int f = t + i * 256;
                int r = f >> 3, cc = (f & 7) * 8;
                cp_async16(Kd + r*KLDH + cc, Kc  + (size_t)r*DK + cc);
                cp_async16(Vd + r*VLDH + cc, Vtc + (size_t)r*nk + cc);
            }
            cp_commit();
            cp_wait<1>();
        } else {
            cp_wait<0>();
        }
        __syncthreads();

        const __half* K = Ksh0 + buf * AK_SZ;
        const __half* V = Vsh0 + buf * AV_SZ;

        // ---- S = Q @ K^T (pre-scaled) : 8 n-tiles x 4 k-blocks --------------
        float s[8][4];
        #pragma unroll
        for (int n = 0; n < 8; n++) {
            s[n][0] = 0.f; s[n][1] = 0.f; s[n][2] = 0.f; s[n][3] = 0.f;
            const __half* Kn = K + (8*n + g) * KLDH;
            #pragma unroll
            for (int j = 0; j < 4; j++) {
                unsigned b0 = *(const unsigned*)(Kn + 16*j + 2*tig);
                unsigned b1 = *(const unsigned*)(Kn + 16*j + 8 + 2*tig);
                mma_f16(s[n], qa[j], b0, b1);
            }
        }

        // ---- online softmax in registers -----------------------------------
        float mx0 = m0, mx1 = m1;
        #pragma unroll
        for (int n = 0; n < 8; n++) {
            mx0 = fmaxf(mx0, fmaxf(s[n][0], s[n][1]));
            mx1 = fmaxf(mx1, fmaxf(s[n][2], s[n][3]));
        }
        mx0 = fmaxf(mx0, __shfl_xor_sync(0xffffffffu, mx0, 1));
        mx0 = fmaxf(mx0, __shfl_xor_sync(0xffffffffu, mx0, 2));
        mx1 = fmaxf(mx1, __shfl_xor_sync(0xffffffffu, mx1, 1));
        mx1 = fmaxf(mx1, __shfl_xor_sync(0xffffffffu, mx1, 2));
        float alpha0 = __expf(m0 - mx0);
        float alpha1 = __expf(m1 - mx1);
        m0 = mx0; m1 = mx1;

        float sum0 = 0.f, sum1 = 0.f;
        unsigned pa[4][4];
        #pragma unroll
        for (int n = 0; n < 8; n++) {
            float p0 = __expf(s[n][0] - mx0);
            float p1 = __expf(s[n][1] - mx0);
            float p2 = __expf(s[n][2] - mx1);
            float p3 = __expf(s[n][3] - mx1);
            sum0 += p0 + p1; sum1 += p2 + p3;
            s[n][0] = p0; s[n][1] = p1; s[n][2] = p2; s[n][3] = p3;
        }
        // C-layout -> A-layout: direct (rows g/g+8, col pairs line up)
        #pragma unroll
        for (int j = 0; j < 4; j++) {
            pa[j][0] = packh2(s[2*j][0],   s[2*j][1]);     // row g,   k lo
            pa[j][1] = packh2(s[2*j][2],   s[2*j][3]);     // row g+8, k lo
            pa[j][2] = packh2(s[2*j+1][0], s[2*j+1][1]);   // row g,   k hi
            pa[j][3] = packh2(s[2*j+1][2], s[2*j+1][3]);   // row g+8, k hi
        }
        sum0 += __shfl_xor_sync(0xffffffffu, sum0, 1);
        sum0 += __shfl_xor_sync(0xffffffffu, sum0, 2);
        sum1 += __shfl_xor_sync(0xffffffffu, sum1, 1);
        sum1 += __shfl_xor_sync(0xffffffffu, sum1, 2);
        l0 = l0 * alpha0 + sum0;
        l1 = l1 * alpha1 + sum1;

        #pragma unroll
        for (int n = 0; n < 8; n++) {
            o[n][0] *= alpha0; o[n][1] *= alpha0;
            o[n][2] *= alpha1; o[n][3] *= alpha1;
        }

        // ---- O += P @ V  (B-fragments contiguous in transposed V) -----------
        #pragma unroll
        for (int n = 0; n < 8; n++) {
            const __half* Vn = V + (8*n + g) * VLDH;    // Vt row = output col d
            #pragma unroll
            for (int j = 0; j < 4; j++) {
                unsigned b0 = *(const unsigned*)(Vn + 16*j + 2*tig);
                unsigned b1 = *(const unsigned*)(Vn + 16*j + 8 + 2*tig);
                mma_f16(o[n], pa[j], b0, b1);
            }
        }
        __syncthreads();
    }

    // ---- epilogue: normalize + merge heads (direct from registers) ---------
    float inv0 = 1.f / l0;
    float inv1 = 1.f / l1;
    int b = bh >> 4, h = bh & 15;
    float* ob = out + ((size_t)(b * nq) + q0 + w*16) * DIM + h * DK;
    #pragma unroll
    for (int n = 0; n < 8; n++) {
        float2 v0 = make_float2(o[n][0] * inv0, o[n][1] * inv0);
        float2 v1 = make_float2(o[n][2] * inv1, o[n][3] * inv1);
        *(float2*)(ob + (size_t)g * DIM + 8*n + 2*tig) = v0;
        *(float2*)(ob + (size_t)(g + 8) * DIM + 8*n + 2*tig) = v1;
    }
}

// ---------------- host launch ------------------------------------------------
extern "C" void kernel_launch(void* const* d_in, const int* in_sizes, int n_in,
                              void* d_out, int out_size)
{
    (void)in_sizes; (void)n_in; (void)out_size;
    const float* text   = (const float*)d_in[0];
    const float* vision = (const float*)d_in[1];
    const float* n1g = (const float*)d_in[2];
    const float* n1b = (const float*)d_in[3];
    const float* n2g = (const float*)d_in[4];
    const float* n2b = (const float*)d_in[5];
    const float* Wq1 = (const float*)d_in[6];
    const float* bq1 = (const float*)d_in[7];
    const float* Wk1 = (const float*)d_in[8];
    const float* bk1 = (const float*)d_in[9];
    const float* Wv1 = (const float*)d_in[10];
    const float* bv1 = (const float*)d_in[11];
    const float* Wq2 = (const float*)d_in[12];
    const float* bq2 = (const float*)d_in[13];
    const float* Wk2 = (const float*)d_in[14];
    const float* bk2 = (const float*)d_in[15];
    const float* Wv2 = (const float*)d_in[16];
    const float* bv2 = (const float*)d_in[17];
    float* out = (float*)d_out;

    __half *tn, *vn, *tq, *tk, *tv, *vq, *vk, *vv, *wc;
    cudaGetSymbolAddress((void**)&tn, g_tn);
    cudaGetSymbolAddress((void**)&vn, g_vn);
    cudaGetSymbolAddress((void**)&tq, g_tq);
    cudaGetSymbolAddress((void**)&tk, g_tk);
    cudaGetSymbolAddress((void**)&tv, g_tv);
    cudaGetSymbolAddress((void**)&vq, g_vq);
    cudaGetSymbolAddress((void**)&vk, g_vk);
    cudaGetSymbolAddress((void**)&vv, g_vv);
    cudaGetSymbolAddress((void**)&wc, g_wc);

    const size_t A1 = (size_t)BATCH * NT * DIM;
    const size_t A2 = (size_t)BATCH * NV * DIM;
    const size_t WSZ = (size_t)DIM * DIM;

    // residual passthrough
    cudaMemcpyAsync(out + A1 + A2,      text,   A1 * sizeof(float), cudaMemcpyDeviceToDevice, 0);
    cudaMemcpyAsync(out + A1 + A2 + A1, vision, A2 * sizeof(float), cudaMemcpyDeviceToDevice, 0);

    // fp16 weights (one launch)
    half_conv_kernel<<<dim3(WSZ / (256*4), 6), 256>>>(Wq1, Wk1, Wv1, Wq2, Wk2, Wv2, wc);

    ln_kernel<<<BATCH * NT, 256>>>(text,   n1g, n1b, tn);
    ln_kernel<<<BATCH * NV, 256>>>(vision, n2g, n2b, vn);

    cudaFuncSetAttribute(proj_kernel, cudaFuncAttributeMaxDynamicSharedMemorySize, PROJ_SMEM);
    dim3 gt(DIM / PBN, BATCH * NT / PBM, 3);
    dim3 gv(DIM / PBN, BATCH * NV / PBM, 3);
    proj_kernel<<<gt, 256, PROJ_SMEM>>>(tn, wc,          bq1, bk1, bv1, tq, tk, tv, NT);
    proj_kernel<<<gv, 256, PROJ_SMEM>>>(vn, wc + 3*WSZ,  bq2, bk2, bv2, vq, vk, vv, NV);

    cudaFuncSetAttribute(attn_kernel, cudaFuncAttributeMaxDynamicSharedMemorySize, ATT_SMEM);
    attn_kernel<<<dim3(NT / 128, BH), 256, ATT_SMEM>>>(tq, vk, vv, out,      NT, NV);
    attn_kernel<<<dim3(NV / 128, BH), 256, ATT_SMEM>>>(vq, tk, tv, out + A1, NV, NT);
}

// round 7
// speedup vs baseline: 9.6488x; 1.1302x over previous
#include <cuda_runtime.h>
#include <cuda_fp16.h>
#include <mma.h>

using namespace nvcuda;

#define DIM    1024
#define HEADS  16
#define DK     64
#define BATCH  8
#define NT     512
#define NV     1024
#define BH     (BATCH*HEADS)

// ---------------- scratch (static device globals; allocation-free) ----------
__device__ __half g_tn[BATCH*NT*DIM];
__device__ __half g_vn[BATCH*NV*DIM];
__device__ __half g_tq[BH*NT*DK];
__device__ __half g_tk[BH*NT*DK];
__device__ __half g_tv[BH*NT*DK];   // TRANSPOSED: [bh][d][seq]
__device__ __half g_vq[BH*NV*DK];
__device__ __half g_vk[BH*NV*DK];
__device__ __half g_vv[BH*NV*DK];   // TRANSPOSED: [bh][d][seq]
__device__ __half g_wc[6*DIM*DIM];  // fp16 weights

// ---------------- async / mma helpers ---------------------------------------
__device__ __forceinline__ void cp_async16(void* smem, const void* gmem) {
    unsigned s = (unsigned)__cvta_generic_to_shared(smem);
    asm volatile("cp.async.ca.shared.global [%0], [%1], 16;\n" :: "r"(s), "l"(gmem));
}
__device__ __forceinline__ void cp_commit() { asm volatile("cp.async.commit_group;\n"); }
template<int N> __device__ __forceinline__ void cp_wait() {
    asm volatile("cp.async.wait_group %0;\n" :: "n"(N));
}
__device__ __forceinline__ void mma_f16(float* d, const unsigned* a, unsigned b0, unsigned b1) {
    asm volatile(
        "mma.sync.aligned.m16n8k16.row.col.f32.f16.f16.f32 "
        "{%0,%1,%2,%3}, {%4,%5,%6,%7}, {%8,%9}, {%0,%1,%2,%3};\n"
        : "+f"(d[0]), "+f"(d[1]), "+f"(d[2]), "+f"(d[3])
        : "r"(a[0]), "r"(a[1]), "r"(a[2]), "r"(a[3]), "r"(b0), "r"(b1));
}
__device__ __forceinline__ void ldmat4(unsigned& r0, unsigned& r1, unsigned& r2, unsigned& r3,
                                       unsigned addr) {
    asm volatile("ldmatrix.sync.aligned.m8n8.x4.shared.b16 {%0,%1,%2,%3}, [%4];"
                 : "=r"(r0), "=r"(r1), "=r"(r2), "=r"(r3) : "r"(addr));
}
__device__ __forceinline__ unsigned packh2(float lo, float hi) {
    __half2 h = __floats2half2_rn(lo, hi);
    return *(unsigned*)&h;
}

// ---------------- fp32 -> fp16 weight conversion (all 6, one launch) --------
__global__ void half_conv_kernel(const float* s0, const float* s1, const float* s2,
                                 const float* s3, const float* s4, const float* s5,
                                 __half* __restrict__ dst)
{
    int w = blockIdx.y;
    const float* src = w == 0 ? s0 : w == 1 ? s1 : w == 2 ? s2 : w == 3 ? s3 : w == 4 ? s4 : s5;
    int i = blockIdx.x * blockDim.x + threadIdx.x;
    float4 v = ((const float4*)src)[i];
    uint2 o;
    o.x = packh2(v.x, v.y);
    o.y = packh2(v.z, v.w);
    ((uint2*)(dst + (size_t)w * DIM * DIM))[i] = o;
}

// ---------------- LayerNorm (both modalities, one launch) --------------------
__global__ void ln_kernel(const float* __restrict__ xt, const float* __restrict__ xv,
                          const float* g1, const float* b1,
                          const float* g2, const float* b2,
                          __half* __restrict__ yt, __half* __restrict__ yv)
{
    int sel = blockIdx.y;
    int row = blockIdx.x;
    if (sel == 0 && row >= BATCH*NT) return;
    const float* x = sel == 0 ? xt : xv;
    const float* g = sel == 0 ? g1 : g2;
    const float* b = sel == 0 ? b1 : b2;
    __half* y      = sel == 0 ? yt : yv;

    int t = threadIdx.x;
    const float4* xr = (const float4*)(x + (size_t)row * DIM);
    float4 xvv = xr[t];

    float s  = xvv.x + xvv.y + xvv.z + xvv.w;
    float sq = xvv.x*xvv.x + xvv.y*xvv.y + xvv.z*xvv.z + xvv.w*xvv.w;

    __shared__ float red[16];
    #pragma unroll
    for (int o = 16; o; o >>= 1) {
        s  += __shfl_xor_sync(0xffffffffu, s,  o);
        sq += __shfl_xor_sync(0xffffffffu, sq, o);
    }
    int wid = t >> 5, lid = t & 31;
    if (lid == 0) { red[wid] = s; red[8 + wid] = sq; }
    __syncthreads();
    if (t == 0) {
        float S = 0.f, SQ = 0.f;
        #pragma unroll
        for (int i = 0; i < 8; i++) { S += red[i]; SQ += red[8 + i]; }
        red[0] = S; red[8] = SQ;
    }
    __syncthreads();
    float mu  = red[0] * (1.f / DIM);
    float var = red[8] * (1.f / DIM) - mu * mu;
    float inv = rsqrtf(var + 1e-5f);

    float4 gv = ((const float4*)g)[t];
    float4 bv = ((const float4*)b)[t];
    uint2 o;
    o.x = packh2((xvv.x - mu) * inv * gv.x + bv.x, (xvv.y - mu) * inv * gv.y + bv.y);
    o.y = packh2((xvv.z - mu) * inv * gv.z + bv.z, (xvv.w - mu) * inv * gv.w + bv.w);
    ((uint2*)(y + (size_t)row * DIM))[t] = o;
}

// ---------------- Projection GEMM v5 -----------------------------------------
// Block 128x128, BK=64, 8 warps with 32x64 tiles (64 acc regs), 2 CTAs/SM.
// grid.z = 0..5 : (q,k,v) x (text, vision). v stored transposed [bh][d][seq].
#define PBM 128
#define PBN 128
#define PBK 64
#define PLDH 72
#define PASZ (PBM*PLDH)
#define PBSZ (PBN*PLDH)
#define PSTG (PASZ+PBSZ)
#define PROJ_SMEM (2*PSTG*2)     // 73,728 B (Csh alias 67,584 B fits)

__global__ __launch_bounds__(256, 2) void proj_kernel(
    const __half* __restrict__ Xt, const __half* __restrict__ Xv,
    const __half* __restrict__ Wbase,
    const float* bq1, const float* bk1, const float* bv1,
    const float* bq2, const float* bk2, const float* bv2,
    __half* tq, __half* tk, __half* tv,
    __half* vq, __half* vk, __half* vv)
{
    int z = blockIdx.z;
    bool is_text = z < 3;
    int seqlen = is_text ? NT : NV;
    if (is_text && blockIdx.y >= (BATCH*NT)/PBM) return;

    const __half* X = is_text ? Xt : Xv;
    const __half* W = Wbase + (size_t)z * DIM * DIM;
    int zz = is_text ? z : z - 3;
    const float* bias = is_text ? (zz == 0 ? bq1 : zz == 1 ? bk1 : bv1)
                                : (zz == 0 ? bq2 : zz == 1 ? bk2 : bv2);
    __half* out       = is_text ? (zz == 0 ? tq : zz == 1 ? tk : tv)
                                : (zz == 0 ? vq : zz == 1 ? vk : vv);

    extern __shared__ char smraw[];
    __half* sm = (__half*)smraw;
    float* Csh = (float*)smraw;              // epilogue alias, ld=132

    int t = threadIdx.x;
    int row0 = blockIdx.y * PBM;
    int col0 = blockIdx.x * PBN;
    int wid = t >> 5;
    int warpM = wid >> 1;                    // 0..3 : 32-row slab
    int warpN = wid & 1;                     // 0..1 : 64-col slab

    wmma::fragment<wmma::accumulator, 16, 16, 16, float> acc[2][4];
    #pragma unroll
    for (int mi = 0; mi < 2; mi++)
        #pragma unroll
        for (int nj = 0; nj < 4; nj++)
            wmma::fill_fragment(acc[mi][nj], 0.0f);

    auto stage = [&](int s, int k0) {
        __half* Ad = sm + s * PSTG;
        __half* Bd = Ad + PASZ;
        #pragma unroll
        for (int i = 0; i < 4; i++) {
            int f = t + i * 256;             // 0..1023 (A: 128 rows x 8 chunks)
            int r = f >> 3, c = (f & 7) * 8;
            cp_async16(Ad + r*PLDH + c, X + (size_t)(row0 + r)*DIM + k0 + c);
        }
        #pragma unroll
        for (int i = 0; i < 4; i++) {
            int f = t + i * 256;             // B: 128 rows x 8 chunks
            int r = f >> 3, c = (f & 7) * 8;
            cp_async16(Bd + r*PLDH + c, W + (size_t)(col0 + r)*DIM + k0 + c);
        }
    };

    stage(0, 0);
    cp_commit();

    #pragma unroll 1
    for (int kt = 0; kt < DIM/PBK; kt++) {
        int buf = kt & 1;
        if (kt + 1 < DIM/PBK) {
            stage(buf ^ 1, (kt + 1) * PBK);
            cp_commit();
            cp_wait<1>();
        } else {
            cp_wait<0>();
        }
        __syncthreads();

        __half* A = sm + buf * PSTG;
        __half* B = A + PASZ;
        #pragma unroll
        for (int kk = 0; kk < 4; kk++) {
            wmma::fragment<wmma::matrix_a, 16, 16, 16, __half, wmma::row_major> a[2];
            wmma::fragment<wmma::matrix_b, 16, 16, 16, __half, wmma::col_major> bf[4];
            #pragma unroll
            for (int mi = 0; mi < 2; mi++)
                wmma::load_matrix_sync(a[mi], A + (warpM*32 + mi*16)*PLDH + kk*16, PLDH);
            #pragma unroll
            for (int nj = 0; nj < 4; nj++)
                wmma::load_matrix_sync(bf[nj], B + (warpN*64 + nj*16)*PLDH + kk*16, PLDH);
            #pragma unroll
            for (int mi = 0; mi < 2; mi++)
                #pragma unroll
                for (int nj = 0; nj < 4; nj++)
                    wmma::mma_sync(acc[mi][nj], a[mi], bf[nj], acc[mi][nj]);
        }
        __syncthreads();
    }

    // epilogue: acc -> Csh (fp32) -> bias + fp16 store with head scatter
    #pragma unroll
    for (int mi = 0; mi < 2; mi++)
        #pragma unroll
        for (int nj = 0; nj < 4; nj++)
            wmma::store_matrix_sync(Csh + (warpM*32 + mi*16)*132 + warpN*64 + nj*16,
                                    acc[mi][nj], 132, wmma::mem_row_major);
    __syncthreads();

    bool is_v = (zz == 2);
    #pragma unroll
    for (int i = 0; i < 16; i++) {
        int f = t + i * 256;                 // 0..4095 float4s over 128x128
        int r = f >> 5, c = (f & 31) * 4;
        float4 v = *(float4*)(Csh + r*132 + c);
        int jg = col0 + c;
        float4 bb = *(const float4*)(bias + jg);
        v.x += bb.x; v.y += bb.y; v.z += bb.z; v.w += bb.w;
        int gr = row0 + r;
        int bidx = gr / seqlen;
        int n = gr - bidx * seqlen;
        int h = jg >> 6;
        int d = jg & 63;
        int bh = bidx * HEADS + h;
        if (!is_v) {
            uint2 o;
            o.x = packh2(v.x, v.y);
            o.y = packh2(v.z, v.w);
            *(uint2*)(out + ((size_t)bh * seqlen + n) * DK + d) = o;
        } else {
            __half* vt = out + ((size_t)bh * DK + d) * seqlen + n;
            vt[0]        = __float2half_rn(v.x);
            vt[seqlen]   = __float2half_rn(v.y);
            vt[2*seqlen] = __float2half_rn(v.z);
            vt[3*seqlen] = __float2half_rn(v.w);
        }
    }
}

// ---------------- Flash cross-attention v6: ldmatrix + merged launch ---------
#define QLDH 72
#define KLDH 72
#define VLDH 72
#define AQ_SZ  (128*QLDH)
#define AK_SZ  (64*KLDH)
#define AV_SZ  (64*VLDH)
#define ATT_SMEM ((AQ_SZ + 2*AK_SZ + 2*AV_SZ) * 2)   // 55,296 B

__global__ __launch_bounds__(256, 2) void attn_kernel(
    const __half* __restrict__ tq, const __half* __restrict__ tk, const __half* __restrict__ tv,
    const __half* __restrict__ vq, const __half* __restrict__ vk, const __half* __restrict__ vv,
    float* __restrict__ outbase)
{
    int z = blockIdx.z;
    int nq = z == 0 ? NT : NV;
    int nk = z == 0 ? NV : NT;
    if (blockIdx.x >= (nq >> 7)) return;
    const __half* Qg  = z == 0 ? tq : vq;
    const __half* Kg  = z == 0 ? vk : tk;
    const __half* Vtg = z == 0 ? vv : tv;
    float* out = outbase + (z == 0 ? 0 : (size_t)BATCH*NT*DIM);

    extern __shared__ char smraw[];
    __half* smh  = (__half*)smraw;
    __half* Qsh  = smh;
    __half* Ksh0 = smh + AQ_SZ;
    __half* Vsh0 = Ksh0 + 2*AK_SZ;

    int t = threadIdx.x;
    int w = t >> 5;
    int lane = t & 31;
    int g = lane >> 2;            // row group 0..7
    int tig = lane & 3;           // thread-in-group
    int bh = blockIdx.y;
    int q0 = blockIdx.x * 128;

    const __half* Qb  = Qg  + ((size_t)bh * nq + q0) * DK;
    const __half* Kb  = Kg  + (size_t)bh * nk * DK;
    const __half* Vtb = Vtg + (size_t)bh * DK * nk;   // [d][kv]

    #pragma unroll
    for (int i = 0; i < 4; i++) {
        int f = t + i * 256;                 // 0..1023 16B-chunks
        int r = f >> 3, c = (f & 7) * 8;
        cp_async16(Qsh + r*QLDH + c, Qb + (size_t)r*DK + c);
    }
    #pragma unroll
    for (int i = 0; i < 2; i++) {
        int f = t + i * 256;                 // 0..511
        int r = f >> 3, c = (f & 7) * 8;
        cp_async16(Ksh0 + r*KLDH + c, Kb + (size_t)r*DK + c);
        cp_async16(Vsh0 + r*VLDH + c, Vtb + (size_t)r*nk + c);
    }
    cp_commit();
    cp_wait<0>();
    __syncthreads();

    // Q fragments: 4 k-blocks of 16; scale 1/8 folded in (exact in fp16)
    unsigned qa[4][4];
    {
        const __half2 sc = __float2half2_rn(0.125f);
        const __half* q0p = Qsh + (w*16 + g) * QLDH;
        const __half* q1p = Qsh + (w*16 + g + 8) * QLDH;
        #pragma unroll
        for (int j = 0; j < 4; j++) {
            __half2 a0 = __hmul2(*(const __half2*)(q0p + 16*j + 2*tig), sc);
            __half2 a1 = __hmul2(*(const __half2*)(q1p + 16*j + 2*tig), sc);
            __half2 a2 = __hmul2(*(const __half2*)(q0p + 16*j + 8 + 2*tig), sc);
            __half2 a3 = __hmul2(*(const __half2*)(q1p + 16*j + 8 + 2*tig), sc);
            qa[j][0] = *(unsigned*)&a0;
            qa[j][1] = *(unsigned*)&a1;
            qa[j][2] = *(unsigned*)&a2;
            qa[j][3] = *(unsigned*)&a3;
        }
    }

    // ldmatrix lane-constant address parts: tile t4 = lane>>3 (0..3)
    //   rows handled: 8*(t4>>1) + (lane&7)  ; column byte offset: (t4&1)*16
    unsigned lrow = 8*((lane >> 4) & 1) + (lane & 7);
    unsigned lcol = ((lane >> 3) & 1) * 16;   // bytes

    float o[8][4];
    #pragma unroll
    for (int n = 0; n < 8; n++)
        #pragma unroll
        for (int e = 0; e < 4; e++) o[n][e] = 0.f;
    float m0 = -1e30f, m1 = -1e30f, l0 = 0.f, l1 = 0.f;

    int nch = nk >> 6;
    #pragma unroll 1
    for (int c = 0; c < nch; c++) {
        int buf = c & 1;
        if (c + 1 < nch) {
            const __half* Kc  = Kb  + (size_t)(c + 1) * 64 * DK;
            const __half* Vtc = Vtb + (size_t)(c + 1) * 64;
            __half* Kd = Ksh0 + (buf ^ 1) * AK_SZ;
            __half* Vd = Vsh0 + (buf ^ 1) * AV_SZ;
            #pragma unroll
            for (int i = 0; i < 2; i++) {
                int f = t + i * 256;
                int r = f >> 3, cc = (f & 7) * 8;
                cp_async16(Kd + r*KLDH + cc, Kc  + (size_t)r*DK + cc);
                cp_async16(Vd + r*VLDH + cc, Vtc + (size_t)r*nk + cc);
            }
            cp_commit();
            cp_wait<1>();
        } else {
            cp_wait<0>();
        }
        __syncthreads();

        const __half* K = Ksh0 + buf * AK_SZ;
        const __half* V = Vsh0 + buf * AV_SZ;
        unsigned kbase = (unsigned)__cvta_generic_to_shared(K) + lrow*KLDH*2 + lcol;
        unsigned vbase = (unsigned)__cvta_generic_to_shared(V) + lrow*VLDH*2 + lcol;

        // ---- S = Q @ K^T (pre-scaled): ldmatrix.x4 gives 2 n-tiles per op ---
        float s[8][4];
        #pragma unroll
        for (int n = 0; n < 8; n++) {
            s[n][0] = 0.f; s[n][1] = 0.f; s[n][2] = 0.f; s[n][3] = 0.f;
        }
        #pragma unroll
        for (int j = 0; j < 4; j++) {
            #pragma unroll
            for (int a = 0; a < 4; a++) {
                unsigned b0, b1, b2, b3;
                ldmat4(b0, b1, b2, b3, kbase + (16*a*KLDH + 16*j)*2);
                mma_f16(s[2*a],   qa[j], b0, b1);
                mma_f16(s[2*a+1], qa[j], b2, b3);
            }
        }

        // ---- online softmax in registers -----------------------------------
        float mx0 = m0, mx1 = m1;
        #pragma unroll
        for (int n = 0; n < 8; n++) {
            mx0 = fmaxf(mx0, fmaxf(s[n][0], s[n][1]));
            mx1 = fmaxf(mx1, fmaxf(s[n][2], s[n][3]));
        }
        mx0 = fmaxf(mx0, __shfl_xor_sync(0xffffffffu, mx0, 1));
        mx0 = fmaxf(mx0, __shfl_xor_sync(0xffffffffu, mx0, 2));
        mx1 = fmaxf(mx1, __shfl_xor_sync(0xffffffffu, mx1, 1));
        mx1 = fmaxf(mx1, __shfl_xor_sync(0xffffffffu, mx1, 2));
        float alpha0 = __expf(m0 - mx0);
        float alpha1 = __expf(m1 - mx1);
        m0 = mx0; m1 = mx1;

        float sum0 = 0.f, sum1 = 0.f;
        unsigned pa[4][4];
        #pragma unroll
        for (int n = 0; n < 8; n++) {
            float p0 = __expf(s[n][0] - mx0);
            float p1 = __expf(s[n][1] - mx0);
            float p2 = __expf(s[n][2] - mx1);
            float p3 = __expf(s[n][3] - mx1);
            sum0 += p0 + p1; sum1 += p2 + p3;
            s[n][0] = p0; s[n][1] = p1; s[n][2] = p2; s[n][3] = p3;
        }
        #pragma unroll
        for (int j = 0; j < 4; j++) {
            pa[j][0] = packh2(s[2*j][0],   s[2*j][1]);
            pa[j][1] = packh2(s[2*j][2],   s[2*j][3]);
            pa[j][2] = packh2(s[2*j+1][0], s[2*j+1][1]);
            pa[j][3] = packh2(s[2*j+1][2], s[2*j+1][3]);
        }
        sum0 += __shfl_xor_sync(0xffffffffu, sum0, 1);
        sum0 += __shfl_xor_sync(0xffffffffu, sum0, 2);
        sum1 += __shfl_xor_sync(0xffffffffu, sum1, 1);
        sum1 += __shfl_xor_sync(0xffffffffu, sum1, 2);
        l0 = l0 * alpha0 + sum0;
        l1 = l1 * alpha1 + sum1;

        #pragma unroll
        for (int n = 0; n < 8; n++) {
            o[n][0] *= alpha0; o[n][1] *= alpha0;
            o[n][2] *= alpha1; o[n][3] *= alpha1;
        }

        // ---- O += P @ V (ldmatrix on transposed V) --------------------------
        #pragma unroll
        for (int j = 0; j < 4; j++) {
            #pragma unroll
            for (int a = 0; a < 4; a++) {
                unsigned b0, b1, b2, b3;
                ldmat4(b0, b1, b2, b3, vbase + (16*a*VLDH + 16*j)*2);
                mma_f16(o[2*a],   pa[j], b0, b1);
                mma_f16(o[2*a+1], pa[j], b2, b3);
            }
        }
        __syncthreads();
    }

    // ---- epilogue: normalize + merge heads ----------------------------------
    float inv0 = 1.f / l0;
    float inv1 = 1.f / l1;
    int b = bh >> 4, h = bh & 15;
    float* ob = out + ((size_t)(b * nq) + q0 + w*16) * DIM + h * DK;
    #pragma unroll
    for (int n = 0; n < 8; n++) {
        float2 v0 = make_float2(o[n][0] * inv0, o[n][1] * inv0);
        float2 v1 = make_float2(o[n][2] * inv1, o[n][3] * inv1);
        *(float2*)(ob + (size_t)g * DIM + 8*n + 2*tig) = v0;
        *(float2*)(ob + (size_t)(g + 8) * DIM + 8*n + 2*tig) = v1;
    }
}

// ---------------- host launch ------------------------------------------------
extern "C" void kernel_launch(void* const* d_in, const int* in_sizes, int n_in,
                              void* d_out, int out_size)
{
    (void)in_sizes; (void)n_in; (void)out_size;
    const float* text   = (const float*)d_in[0];
    const float* vision = (const float*)d_in[1];
    const float* n1g = (const float*)d_in[2];
    const float* n1b = (const float*)d_in[3];
    const float* n2g = (const float*)d_in[4];
    const float* n2b = (const float*)d_in[5];
    const float* Wq1 = (const float*)d_in[6];
    const float* bq1 = (const float*)d_in[7];
    const float* Wk1 = (const float*)d_in[8];
    const float* bk1 = (const float*)d_in[9];
    const float* Wv1 = (const float*)d_in[10];
    const float* bv1 = (const float*)d_in[11];
    const float* Wq2 = (const float*)d_in[12];
    const float* bq2 = (const float*)d_in[13];
    const float* Wk2 = (const float*)d_in[14];
    const float* bk2 = (const float*)d_in[15];
    const float* Wv2 = (const float*)d_in[16];
    const float* bv2 = (const float*)d_in[17];
    float* out = (float*)d_out;

    __half *tn, *vn, *tq, *tk, *tv, *vq, *vk, *vv, *wc;
    cudaGetSymbolAddress((void**)&tn, g_tn);
    cudaGetSymbolAddress((void**)&vn, g_vn);
    cudaGetSymbolAddress((void**)&tq, g_tq);
    cudaGetSymbolAddress((void**)&tk, g_tk);
    cudaGetSymbolAddress((void**)&tv, g_tv);
    cudaGetSymbolAddress((void**)&vq, g_vq);
    cudaGetSymbolAddress((void**)&vk, g_vk);
    cudaGetSymbolAddress((void**)&vv, g_vv);
    cudaGetSymbolAddress((void**)&wc, g_wc);

    const size_t A1 = (size_t)BATCH * NT * DIM;
    const size_t A2 = (size_t)BATCH * NV * DIM;
    const size_t WSZ = (size_t)DIM * DIM;

    // residual passthrough
    cudaMemcpyAsync(out + A1 + A2,      text,   A1 * sizeof(float), cudaMemcpyDeviceToDevice, 0);
    cudaMemcpyAsync(out + A1 + A2 + A1, vision, A2 * sizeof(float), cudaMemcpyDeviceToDevice, 0);

    // fp16 weights (one launch)
    half_conv_kernel<<<dim3(WSZ / (256*4), 6), 256>>>(Wq1, Wk1, Wv1, Wq2, Wk2, Wv2, wc);

    // both layernorms, one launch
    ln_kernel<<<dim3(BATCH * NV, 2), 256>>>(text, vision, n1g, n1b, n2g, n2b, tn, vn);

    // all six projections, one launch
    cudaFuncSetAttribute(proj_kernel, cudaFuncAttributeMaxDynamicSharedMemorySize, PROJ_SMEM);
    dim3 gp(DIM / PBN, BATCH * NV / PBM, 6);    // 8 x 64 x 6 (text y>=32 exits)
    proj_kernel<<<gp, 256, PROJ_SMEM>>>(tn, vn, wc,
                                        bq1, bk1, bv1, bq2, bk2, bv2,
                                        tq, tk, tv, vq, vk, vv);

    // both attention directions, one launch
    cudaFuncSetAttribute(attn_kernel, cudaFuncAttributeMaxDynamicSharedMemorySize, ATT_SMEM);
    dim3 ga(NV / 128, BH, 2);                   // 8 x 128 x 2 (text x>=4 exits)
    attn_kernel<<<ga, 256, ATT_SMEM>>>(tq, tk, tv, vq, vk, vv, out);
}

// round 8
// speedup vs baseline: 10.3284x; 1.0704x over previous
#include <cuda_runtime.h>
#include <cuda_fp16.h>
#include <mma.h>

using namespace nvcuda;

#define DIM    1024
#define HEADS  16
#define DK     64
#define BATCH  8
#define NT     512
#define NV     1024
#define BH     (BATCH*HEADS)

// ---------------- scratch (static device globals; allocation-free) ----------
__device__ __half g_tn[BATCH*NT*DIM];
__device__ __half g_vn[BATCH*NV*DIM];
__device__ __half g_tq[BH*NT*DK];
__device__ __half g_tk[BH*NT*DK];
__device__ __half g_tv[BH*NT*DK];   // TRANSPOSED: [bh][d][seq]
__device__ __half g_vq[BH*NV*DK];
__device__ __half g_vk[BH*NV*DK];
__device__ __half g_vv[BH*NV*DK];   // TRANSPOSED: [bh][d][seq]
__device__ __half g_wc[6*DIM*DIM];  // fp16 weights

// ---------------- async / mma helpers ---------------------------------------
__device__ __forceinline__ void cp_async16(void* smem, const void* gmem) {
    unsigned s = (unsigned)__cvta_generic_to_shared(smem);
    asm volatile("cp.async.ca.shared.global [%0], [%1], 16;\n" :: "r"(s), "l"(gmem));
}
__device__ __forceinline__ void cp_commit() { asm volatile("cp.async.commit_group;\n"); }
template<int N> __device__ __forceinline__ void cp_wait() {
    asm volatile("cp.async.wait_group %0;\n" :: "n"(N));
}
__device__ __forceinline__ void mma_f16(float* d, const unsigned* a, unsigned b0, unsigned b1) {
    asm volatile(
        "mma.sync.aligned.m16n8k16.row.col.f32.f16.f16.f32 "
        "{%0,%1,%2,%3}, {%4,%5,%6,%7}, {%8,%9}, {%0,%1,%2,%3};\n"
        : "+f"(d[0]), "+f"(d[1]), "+f"(d[2]), "+f"(d[3])
        : "r"(a[0]), "r"(a[1]), "r"(a[2]), "r"(a[3]), "r"(b0), "r"(b1));
}
__device__ __forceinline__ void ldmat4(unsigned& r0, unsigned& r1, unsigned& r2, unsigned& r3,
                                       unsigned addr) {
    asm volatile("ldmatrix.sync.aligned.m8n8.x4.shared.b16 {%0,%1,%2,%3}, [%4];"
                 : "=r"(r0), "=r"(r1), "=r"(r2), "=r"(r3) : "r"(addr));
}
__device__ __forceinline__ unsigned packh2(float lo, float hi) {
    __half2 h = __floats2half2_rn(lo, hi);
    return *(unsigned*)&h;
}

// ---------------- fp32 -> fp16 weight conversion (all 6, one launch) --------
__global__ void half_conv_kernel(const float* s0, const float* s1, const float* s2,
                                 const float* s3, const float* s4, const float* s5,
                                 __half* __restrict__ dst)
{
    int w = blockIdx.y;
    const float* src = w == 0 ? s0 : w == 1 ? s1 : w == 2 ? s2 : w == 3 ? s3 : w == 4 ? s4 : s5;
    int i = blockIdx.x * blockDim.x + threadIdx.x;
    float4 v = ((const float4*)src)[i];
    uint2 o;
    o.x = packh2(v.x, v.y);
    o.y = packh2(v.z, v.w);
    ((uint2*)(dst + (size_t)w * DIM * DIM))[i] = o;
}

// ---------------- LayerNorm + residual passthrough (one launch) --------------
// Also writes the fp32 residual copy (replaces the slow D2D memcpy nodes).
__global__ void ln_kernel(const float* __restrict__ xt, const float* __restrict__ xv,
                          const float* g1, const float* b1,
                          const float* g2, const float* b2,
                          __half* __restrict__ yt, __half* __restrict__ yv,
                          float* __restrict__ rt, float* __restrict__ rv)
{
    int sel = blockIdx.y;
    int row = blockIdx.x;
    if (sel == 0 && row >= BATCH*NT) return;
    const float* x = sel == 0 ? xt : xv;
    const float* g = sel == 0 ? g1 : g2;
    const float* b = sel == 0 ? b1 : b2;
    __half* y      = sel == 0 ? yt : yv;
    float* r       = sel == 0 ? rt : rv;

    int t = threadIdx.x;
    const float4* xr = (const float4*)(x + (size_t)row * DIM);
    float4 xvv = xr[t];

    // residual passthrough (free read — already in registers)
    ((float4*)(r + (size_t)row * DIM))[t] = xvv;

    float s  = xvv.x + xvv.y + xvv.z + xvv.w;
    float sq = xvv.x*xvv.x + xvv.y*xvv.y + xvv.z*xvv.z + xvv.w*xvv.w;

    __shared__ float red[16];
    #pragma unroll
    for (int o = 16; o; o >>= 1) {
        s  += __shfl_xor_sync(0xffffffffu, s,  o);
        sq += __shfl_xor_sync(0xffffffffu, sq, o);
    }
    int wid = t >> 5, lid = t & 31;
    if (lid == 0) { red[wid] = s; red[8 + wid] = sq; }
    __syncthreads();
    if (t == 0) {
        float S = 0.f, SQ = 0.f;
        #pragma unroll
        for (int i = 0; i < 8; i++) { S += red[i]; SQ += red[8 + i]; }
        red[0] = S; red[8] = SQ;
    }
    __syncthreads();
    float mu  = red[0] * (1.f / DIM);
    float var = red[8] * (1.f / DIM) - mu * mu;
    float inv = rsqrtf(var + 1e-5f);

    float4 gv = ((const float4*)g)[t];
    float4 bv = ((const float4*)b)[t];
    uint2 o;
    o.x = packh2((xvv.x - mu) * inv * gv.x + bv.x, (xvv.y - mu) * inv * gv.y + bv.y);
    o.y = packh2((xvv.z - mu) * inv * gv.z + bv.z, (xvv.w - mu) * inv * gv.w + bv.w);
    ((uint2*)(y + (size_t)row * DIM))[t] = o;
}

// ---------------- Projection GEMM v5 (unchanged from R6) ---------------------
#define PBM 128
#define PBN 128
#define PBK 64
#define PLDH 72
#define PASZ (PBM*PLDH)
#define PBSZ (PBN*PLDH)
#define PSTG (PASZ+PBSZ)
#define PROJ_SMEM (2*PSTG*2)     // 73,728 B

__global__ __launch_bounds__(256, 2) void proj_kernel(
    const __half* __restrict__ Xt, const __half* __restrict__ Xv,
    const __half* __restrict__ Wbase,
    const float* bq1, const float* bk1, const float* bv1,
    const float* bq2, const float* bk2, const float* bv2,
    __half* tq, __half* tk, __half* tv,
    __half* vq, __half* vk, __half* vv)
{
    int z = blockIdx.z;
    bool is_text = z < 3;
    int seqlen = is_text ? NT : NV;
    if (is_text && blockIdx.y >= (BATCH*NT)/PBM) return;

    const __half* X = is_text ? Xt : Xv;
    const __half* W = Wbase + (size_t)z * DIM * DIM;
    int zz = is_text ? z : z - 3;
    const float* bias = is_text ? (zz == 0 ? bq1 : zz == 1 ? bk1 : bv1)
                                : (zz == 0 ? bq2 : zz == 1 ? bk2 : bv2);
    __half* out       = is_text ? (zz == 0 ? tq : zz == 1 ? tk : tv)
                                : (zz == 0 ? vq : zz == 1 ? vk : vv);

    extern __shared__ char smraw[];
    __half* sm = (__half*)smraw;
    float* Csh = (float*)smraw;

    int t = threadIdx.x;
    int row0 = blockIdx.y * PBM;
    int col0 = blockIdx.x * PBN;
    int wid = t >> 5;
    int warpM = wid >> 1;
    int warpN = wid & 1;

    wmma::fragment<wmma::accumulator, 16, 16, 16, float> acc[2][4];
    #pragma unroll
    for (int mi = 0; mi < 2; mi++)
        #pragma unroll
        for (int nj = 0; nj < 4; nj++)
            wmma::fill_fragment(acc[mi][nj], 0.0f);

    auto stage = [&](int s, int k0) {
        __half* Ad = sm + s * PSTG;
        __half* Bd = Ad + PASZ;
        #pragma unroll
        for (int i = 0; i < 4; i++) {
            int f = t + i * 256;
            int r = f >> 3, c = (f & 7) * 8;
            cp_async16(Ad + r*PLDH + c, X + (size_t)(row0 + r)*DIM + k0 + c);
        }
        #pragma unroll
        for (int i = 0; i < 4; i++) {
            int f = t + i * 256;
            int r = f >> 3, c = (f & 7) * 8;
            cp_async16(Bd + r*PLDH + c, W + (size_t)(col0 + r)*DIM + k0 + c);
        }
    };

    stage(0, 0);
    cp_commit();

    #pragma unroll 1
    for (int kt = 0; kt < DIM/PBK; kt++) {
        int buf = kt & 1;
        if (kt + 1 < DIM/PBK) {
            stage(buf ^ 1, (kt + 1) * PBK);
            cp_commit();
            cp_wait<1>();
        } else {
            cp_wait<0>();
        }
        __syncthreads();

        __half* A = sm + buf * PSTG;
        __half* B = A + PASZ;
        #pragma unroll
        for (int kk = 0; kk < 4; kk++) {
            wmma::fragment<wmma::matrix_a, 16, 16, 16, __half, wmma::row_major> a[2];
            wmma::fragment<wmma::matrix_b, 16, 16, 16, __half, wmma::col_major> bf[4];
            #pragma unroll
            for (int mi = 0; mi < 2; mi++)
                wmma::load_matrix_sync(a[mi], A + (warpM*32 + mi*16)*PLDH + kk*16, PLDH);
            #pragma unroll
            for (int nj = 0; nj < 4; nj++)
                wmma::load_matrix_sync(bf[nj], B + (warpN*64 + nj*16)*PLDH + kk*16, PLDH);
            #pragma unroll
            for (int mi = 0; mi < 2; mi++)
                #pragma unroll
                for (int nj = 0; nj < 4; nj++)
                    wmma::mma_sync(acc[mi][nj], a[mi], bf[nj], acc[mi][nj]);
        }
        __syncthreads();
    }

    #pragma unroll
    for (int mi = 0; mi < 2; mi++)
        #pragma unroll
        for (int nj = 0; nj < 4; nj++)
            wmma::store_matrix_sync(Csh + (warpM*32 + mi*16)*132 + warpN*64 + nj*16,
                                    acc[mi][nj], 132, wmma::mem_row_major);
    __syncthreads();

    bool is_v = (zz == 2);
    #pragma unroll
    for (int i = 0; i < 16; i++) {
        int f = t + i * 256;
        int r = f >> 5, c = (f & 31) * 4;
        float4 v = *(float4*)(Csh + r*132 + c);
        int jg = col0 + c;
        float4 bb = *(const float4*)(bias + jg);
        v.x += bb.x; v.y += bb.y; v.z += bb.z; v.w += bb.w;
        int gr = row0 + r;
        int bidx = gr / seqlen;
        int n = gr - bidx * seqlen;
        int h = jg >> 6;
        int d = jg & 63;
        int bh = bidx * HEADS + h;
        if (!is_v) {
            uint2 o;
            o.x = packh2(v.x, v.y);
            o.y = packh2(v.z, v.w);
            *(uint2*)(out + ((size_t)bh * seqlen + n) * DK + d) = o;
        } else {
            __half* vt = out + ((size_t)bh * DK + d) * seqlen + n;
            vt[0]        = __float2half_rn(v.x);
            vt[seqlen]   = __float2half_rn(v.y);
            vt[2*seqlen] = __float2half_rn(v.z);
            vt[3*seqlen] = __float2half_rn(v.w);
        }
    }
}

// ---------------- Flash cross-attention v7: warp M=32 ------------------------
// 128 threads / 4 warps; warp owns 32 q-rows x dk=64 (two 16-row mma sets).
// Each ldmatrix.x4 feeds 4 MMAs -> K/V smem read traffic halved vs v6.
#define QLDH 72
#define KLDH 72
#define VLDH 72
#define AQ_SZ  (128*QLDH)
#define AK_SZ  (64*KLDH)
#define AV_SZ  (64*VLDH)
#define ATT_SMEM ((AQ_SZ + 2*AK_SZ + 2*AV_SZ) * 2)   // 55,296 B

__global__ __launch_bounds__(128, 2) void attn_kernel(
    const __half* __restrict__ tq, const __half* __restrict__ tk, const __half* __restrict__ tv,
    const __half* __restrict__ vq, const __half* __restrict__ vk, const __half* __restrict__ vv,
    float* __restrict__ outbase)
{
    int z = blockIdx.z;
    int nq = z == 0 ? NT : NV;
    int nk = z == 0 ? NV : NT;
    if (blockIdx.x >= (nq >> 7)) return;
    const __half* Qg  = z == 0 ? tq : vq;
    const __half* Kg  = z == 0 ? vk : tk;
    const __half* Vtg = z == 0 ? vv : tv;
    float* out = outbase + (z == 0 ? 0 : (size_t)BATCH*NT*DIM);

    extern __shared__ char smraw[];
    __half* smh  = (__half*)smraw;
    __half* Qsh  = smh;
    __half* Ksh0 = smh + AQ_SZ;
    __half* Vsh0 = Ksh0 + 2*AK_SZ;

    int t = threadIdx.x;          // 0..127
    int w = t >> 5;               // 0..3 -> q rows [w*32, w*32+32)
    int lane = t & 31;
    int g = lane >> 2;
    int tig = lane & 3;
    int bh = blockIdx.y;
    int q0 = blockIdx.x * 128;

    const __half* Qb  = Qg  + ((size_t)bh * nq + q0) * DK;
    const __half* Kb  = Kg  + (size_t)bh * nk * DK;
    const __half* Vtb = Vtg + (size_t)bh * DK * nk;   // [d][kv]

    #pragma unroll
    for (int i = 0; i < 8; i++) {
        int f = t + i * 128;                 // 0..1023 16B-chunks (Q)
        int r = f >> 3, c = (f & 7) * 8;
        cp_async16(Qsh + r*QLDH + c, Qb + (size_t)r*DK + c);
    }
    #pragma unroll
    for (int i = 0; i < 4; i++) {
        int f = t + i * 128;                 // 0..511 (K, Vt)
        int r = f >> 3, c = (f & 7) * 8;
        cp_async16(Ksh0 + r*KLDH + c, Kb + (size_t)r*DK + c);
        cp_async16(Vsh0 + r*VLDH + c, Vtb + (size_t)r*nk + c);
    }
    cp_commit();
    cp_wait<0>();
    __syncthreads();

    // Q fragments: 2 m-sets x 4 k-blocks; scale 1/8 folded in (exact)
    unsigned qa[2][4][4];
    #pragma unroll
    for (int set = 0; set < 2; set++) {
        const __half2 sc = __float2half2_rn(0.125f);
        const __half* q0p = Qsh + (w*32 + set*16 + g) * QLDH;
        const __half* q1p = Qsh + (w*32 + set*16 + g + 8) * QLDH;
        #pragma unroll
        for (int j = 0; j < 4; j++) {
            __half2 a0 = __hmul2(*(const __half2*)(q0p + 16*j + 2*tig), sc);
            __half2 a1 = __hmul2(*(const __half2*)(q1p + 16*j + 2*tig), sc);
            __half2 a2 = __hmul2(*(const __half2*)(q0p + 16*j + 8 + 2*tig), sc);
            __half2 a3 = __hmul2(*(const __half2*)(q1p + 16*j + 8 + 2*tig), sc);
            qa[set][j][0] = *(unsigned*)&a0;
            qa[set][j][1] = *(unsigned*)&a1;
            qa[set][j][2] = *(unsigned*)&a2;
            qa[set][j][3] = *(unsigned*)&a3;
        }
    }

    unsigned lrow = 8*((lane >> 4) & 1) + (lane & 7);
    unsigned lcol = ((lane >> 3) & 1) * 16;   // bytes

    float o[2][8][4];
    #pragma unroll
    for (int set = 0; set < 2; set++)
        #pragma unroll
        for (int n = 0; n < 8; n++)
            #pragma unroll
            for (int e = 0; e < 4; e++) o[set][n][e] = 0.f;
    float m0[2] = {-1e30f, -1e30f}, m1[2] = {-1e30f, -1e30f};
    float l0[2] = {0.f, 0.f},       l1[2] = {0.f, 0.f};

    int nch = nk >> 6;
    #pragma unroll 1
    for (int c = 0; c < nch; c++) {
        int buf = c & 1;
        if (c + 1 < nch) {
            const __half* Kc  = Kb  + (size_t)(c + 1) * 64 * DK;
            const __half* Vtc = Vtb + (size_t)(c + 1) * 64;
            __half* Kd = Ksh0 + (buf ^ 1) * AK_SZ;
            __half* Vd = Vsh0 + (buf ^ 1) * AV_SZ;
            #pragma unroll
            for (int i = 0; i < 4; i++) {
                int f = t + i * 128;
                int r = f >> 3, cc = (f & 7) * 8;
                cp_async16(Kd + r*KLDH + cc, Kc  + (size_t)r*DK + cc);
                cp_async16(Vd + r*VLDH + cc, Vtc + (size_t)r*nk + cc);
            }
            cp_commit();
            cp_wait<1>();
        } else {
            cp_wait<0>();
        }
        __syncthreads();

        const __half* K = Ksh0 + buf * AK_SZ;
        const __half* V = Vsh0 + buf * AV_SZ;
        unsigned kbase = (unsigned)__cvta_generic_to_shared(K) + lrow*KLDH*2 + lcol;
        unsigned vbase = (unsigned)__cvta_generic_to_shared(V) + lrow*VLDH*2 + lcol;

        // ---- S = Q @ K^T : each ldmat4 feeds 4 MMAs (2 n-tiles x 2 m-sets) --
        float s[2][8][4];
        #pragma unroll
        for (int set = 0; set < 2; set++)
            #pragma unroll
            for (int n = 0; n < 8; n++) {
                s[set][n][0] = 0.f; s[set][n][1] = 0.f;
                s[set][n][2] = 0.f; s[set][n][3] = 0.f;
            }
        #pragma unroll
        for (int j = 0; j < 4; j++) {
            #pragma unroll
            for (int a = 0; a < 4; a++) {
                unsigned b0, b1, b2, b3;
                ldmat4(b0, b1, b2, b3, kbase + (16*a*KLDH + 16*j)*2);
                mma_f16(s[0][2*a],   qa[0][j], b0, b1);
                mma_f16(s[0][2*a+1], qa[0][j], b2, b3);
                mma_f16(s[1][2*a],   qa[1][j], b0, b1);
                mma_f16(s[1][2*a+1], qa[1][j], b2, b3);
            }
        }

        // ---- online softmax (per m-set) -------------------------------------
        unsigned pa[2][4][4];
        #pragma unroll
        for (int set = 0; set < 2; set++) {
            float mx0 = m0[set], mx1 = m1[set];
            #pragma unroll
            for (int n = 0; n < 8; n++) {
                mx0 = fmaxf(mx0, fmaxf(s[set][n][0], s[set][n][1]));
                mx1 = fmaxf(mx1, fmaxf(s[set][n][2], s[set][n][3]));
            }
            mx0 = fmaxf(mx0, __shfl_xor_sync(0xffffffffu, mx0, 1));
            mx0 = fmaxf(mx0, __shfl_xor_sync(0xffffffffu, mx0, 2));
            mx1 = fmaxf(mx1, __shfl_xor_sync(0xffffffffu, mx1, 1));
            mx1 = fmaxf(mx1, __shfl_xor_sync(0xffffffffu, mx1, 2));
            float alpha0 = __expf(m0[set] - mx0);
            float alpha1 = __expf(m1[set] - mx1);
            m0[set] = mx0; m1[set] = mx1;

            float sum0 = 0.f, sum1 = 0.f;
            #pragma unroll
            for (int n = 0; n < 8; n++) {
                float p0 = __expf(s[set][n][0] - mx0);
                float p1 = __expf(s[set][n][1] - mx0);
                float p2 = __expf(s[set][n][2] - mx1);
                float p3 = __expf(s[set][n][3] - mx1);
                sum0 += p0 + p1; sum1 += p2 + p3;
                s[set][n][0] = p0; s[set][n][1] = p1;
                s[set][n][2] = p2; s[set][n][3] = p3;
            }
            #pragma unroll
            for (int j = 0; j < 4; j++) {
                pa[set][j][0] = packh2(s[set][2*j][0],   s[set][2*j][1]);
                pa[set][j][1] = packh2(s[set][2*j][2],   s[set][2*j][3]);
                pa[set][j][2] = packh2(s[set][2*j+1][0], s[set][2*j+1][1]);
                pa[set][j][3] = packh2(s[set][2*j+1][2], s[set][2*j+1][3]);
            }
            sum0 += __shfl_xor_sync(0xffffffffu, sum0, 1);
            sum0 += __shfl_xor_sync(0xffffffffu, sum0, 2);
            sum1 += __shfl_xor_sync(0xffffffffu, sum1, 1);
            sum1 += __shfl_xor_sync(0xffffffffu, sum1, 2);
            l0[set] = l0[set] * alpha0 + sum0;
            l1[set] = l1[set] * alpha1 + sum1;

            #pragma unroll
            for (int n = 0; n < 8; n++) {
                o[set][n][0] *= alpha0; o[set][n][1] *= alpha0;
                o[set][n][2] *= alpha1; o[set][n][3] *= alpha1;
            }
        }

        // ---- O += P @ V : each ldmat4 feeds 4 MMAs --------------------------
        #pragma unroll
        for (int j = 0; j < 4; j++) {
            #pragma unroll
            for (int a = 0; a < 4; a++) {
                unsigned b0, b1, b2, b3;
                ldmat4(b0, b1, b2, b3, vbase + (16*a*VLDH + 16*j)*2);
                mma_f16(o[0][2*a],   pa[0][j], b0, b1);
                mma_f16(o[0][2*a+1], pa[0][j], b2, b3);
                mma_f16(o[1][2*a],   pa[1][j], b0, b1);
                mma_f16(o[1][2*a+1], pa[1][j], b2, b3);
            }
        }
        __syncthreads();
    }

    // ---- epilogue: normalize + merge heads ----------------------------------
    int b = bh >> 4, h = bh & 15;
    #pragma unroll
    for (int set = 0; set < 2; set++) {
        float inv0 = 1.f / l0[set];
        float inv1 = 1.f / l1[set];
        float* ob = out + ((size_t)(b * nq) + q0 + w*32 + set*16) * DIM + h * DK;
        #pragma unroll
        for (int n = 0; n < 8; n++) {
            float2 v0 = make_float2(o[set][n][0] * inv0, o[set][n][1] * inv0);
            float2 v1 = make_float2(o[set][n][2] * inv1, o[set][n][3] * inv1);
            *(float2*)(ob + (size_t)g * DIM + 8*n + 2*tig) = v0;
            *(float2*)(ob + (size_t)(g + 8) * DIM + 8*n + 2*tig) = v1;
        }
    }
}

// ---------------- host launch ------------------------------------------------
extern "C" void kernel_launch(void* const* d_in, const int* in_sizes, int n_in,
                              void* d_out, int out_size)
{
    (void)in_sizes; (void)n_in; (void)out_size;
    const float* text   = (const float*)d_in[0];
    const float* vision = (const float*)d_in[1];
    const float* n1g = (const float*)d_in[2];
    const float* n1b = (const float*)d_in[3];
    const float* n2g = (const float*)d_in[4];
    const float* n2b = (const float*)d_in[5];
    const float* Wq1 = (const float*)d_in[6];
    const float* bq1 = (const float*)d_in[7];
    const float* Wk1 = (const float*)d_in[8];
    const float* bk1 = (const float*)d_in[9];
    const float* Wv1 = (const float*)d_in[10];
    const float* bv1 = (const float*)d_in[11];
    const float* Wq2 = (const float*)d_in[12];
    const float* bq2 = (const float*)d_in[13];
    const float* Wk2 = (const float*)d_in[14];
    const float* bk2 = (const float*)d_in[15];
    const float* Wv2 = (const float*)d_in[16];
    const float* bv2 = (const float*)d_in[17];
    float* out = (float*)d_out;

    __half *tn, *vn, *tq, *tk, *tv, *vq, *vk, *vv, *wc;
    cudaGetSymbolAddress((void**)&tn, g_tn);
    cudaGetSymbolAddress((void**)&vn, g_vn);
    cudaGetSymbolAddress((void**)&tq, g_tq);
    cudaGetSymbolAddress((void**)&tk, g_tk);
    cudaGetSymbolAddress((void**)&tv, g_tv);
    cudaGetSymbolAddress((void**)&vq, g_vq);
    cudaGetSymbolAddress((void**)&vk, g_vk);
    cudaGetSymbolAddress((void**)&vv, g_vv);
    cudaGetSymbolAddress((void**)&wc, g_wc);

    const size_t A1 = (size_t)BATCH * NT * DIM;
    const size_t A2 = (size_t)BATCH * NV * DIM;
    const size_t WSZ = (size_t)DIM * DIM;

    // fp16 weights (one launch)
    half_conv_kernel<<<dim3(WSZ / (256*4), 6), 256>>>(Wq1, Wk1, Wv1, Wq2, Wk2, Wv2, wc);

    // both layernorms + residual passthrough, one launch
    ln_kernel<<<dim3(BATCH * NV, 2), 256>>>(text, vision, n1g, n1b, n2g, n2b,
                                            tn, vn,
                                            out + A1 + A2, out + A1 + A2 + A1);

    // all six projections, one launch
    cudaFuncSetAttribute(proj_kernel, cudaFuncAttributeMaxDynamicSharedMemorySize, PROJ_SMEM);
    dim3 gp(DIM / PBN, BATCH * NV / PBM, 6);
    proj_kernel<<<gp, 256, PROJ_SMEM>>>(tn, vn, wc,
                                        bq1, bk1, bv1, bq2, bk2, bv2,
                                        tq, tk, tv, vq, vk, vv);

    // both attention directions, one launch
    cudaFuncSetAttribute(attn_kernel, cudaFuncAttributeMaxDynamicSharedMemorySize, ATT_SMEM);
    dim3 ga(NV / 128, BH, 2);
    attn_kernel<<<ga, 128, ATT_SMEM>>>(tq, tk, tv, vq, vk, vv, out);
}

// round 9
// speedup vs baseline: 10.7827x; 1.0440x over previous
#include <cuda_runtime.h>
#include <cuda_fp16.h>
#include <mma.h>

using namespace nvcuda;

#define DIM    1024
#define HEADS  16
#define DK     64
#define BATCH  8
#define NT     512
#define NV     1024
#define BH     (BATCH*HEADS)

// ---------------- scratch (static device globals; allocation-free) ----------
__device__ __half g_tn[BATCH*NT*DIM];
__device__ __half g_vn[BATCH*NV*DIM];
__device__ __half g_tq[BH*NT*DK];
__device__ __half g_tk[BH*NT*DK];
__device__ __half g_tv[BH*NT*DK];   // TRANSPOSED: [bh][d][seq]
__device__ __half g_vq[BH*NV*DK];
__device__ __half g_vk[BH*NV*DK];
__device__ __half g_vv[BH*NV*DK];   // TRANSPOSED: [bh][d][seq]
__device__ __half g_wc[6*DIM*DIM];  // fp16 weights

// ---------------- async / mma helpers ---------------------------------------
__device__ __forceinline__ void cp_async16(void* smem, const void* gmem) {
    unsigned s = (unsigned)__cvta_generic_to_shared(smem);
    asm volatile("cp.async.ca.shared.global [%0], [%1], 16;\n" :: "r"(s), "l"(gmem));
}
__device__ __forceinline__ void cp_commit() { asm volatile("cp.async.commit_group;\n"); }
template<int N> __device__ __forceinline__ void cp_wait() {
    asm volatile("cp.async.wait_group %0;\n" :: "n"(N));
}
__device__ __forceinline__ void mma_f16(float* d, const unsigned* a, unsigned b0, unsigned b1) {
    asm volatile(
        "mma.sync.aligned.m16n8k16.row.col.f32.f16.f16.f32 "
        "{%0,%1,%2,%3}, {%4,%5,%6,%7}, {%8,%9}, {%0,%1,%2,%3};\n"
        : "+f"(d[0]), "+f"(d[1]), "+f"(d[2]), "+f"(d[3])
        : "r"(a[0]), "r"(a[1]), "r"(a[2]), "r"(a[3]), "r"(b0), "r"(b1));
}
__device__ __forceinline__ void ldmat4(unsigned& r0, unsigned& r1, unsigned& r2, unsigned& r3,
                                       unsigned addr) {
    asm volatile("ldmatrix.sync.aligned.m8n8.x4.shared.b16 {%0,%1,%2,%3}, [%4];"
                 : "=r"(r0), "=r"(r1), "=r"(r2), "=r"(r3) : "r"(addr));
}
__device__ __forceinline__ unsigned packh2(float lo, float hi) {
    __half2 h = __floats2half2_rn(lo, hi);
    return *(unsigned*)&h;
}

// ---------------- fp32 -> fp16 weight conversion (all 6, one launch) --------
__global__ void half_conv_kernel(const float* s0, const float* s1, const float* s2,
                                 const float* s3, const float* s4, const float* s5,
                                 __half* __restrict__ dst)
{
    int w = blockIdx.y;
    const float* src = w == 0 ? s0 : w == 1 ? s1 : w == 2 ? s2 : w == 3 ? s3 : w == 4 ? s4 : s5;
    int i = blockIdx.x * blockDim.x + threadIdx.x;
    float4 v = ((const float4*)src)[i];
    uint2 o;
    o.x = packh2(v.x, v.y);
    o.y = packh2(v.z, v.w);
    ((uint2*)(dst + (size_t)w * DIM * DIM))[i] = o;
}

// ---------------- LayerNorm + residual passthrough (one launch) --------------
__global__ void ln_kernel(const float* __restrict__ xt, const float* __restrict__ xv,
                          const float* g1, const float* b1,
                          const float* g2, const float* b2,
                          __half* __restrict__ yt, __half* __restrict__ yv,
                          float* __restrict__ rt, float* __restrict__ rv)
{
    int sel = blockIdx.y;
    int row = blockIdx.x;
    if (sel == 0 && row >= BATCH*NT) return;
    const float* x = sel == 0 ? xt : xv;
    const float* g = sel == 0 ? g1 : g2;
    const float* b = sel == 0 ? b1 : b2;
    __half* y      = sel == 0 ? yt : yv;
    float* r       = sel == 0 ? rt : rv;

    int t = threadIdx.x;
    const float4* xr = (const float4*)(x + (size_t)row * DIM);
    float4 xvv = xr[t];

    ((float4*)(r + (size_t)row * DIM))[t] = xvv;   // residual passthrough

    float s  = xvv.x + xvv.y + xvv.z + xvv.w;
    float sq = xvv.x*xvv.x + xvv.y*xvv.y + xvv.z*xvv.z + xvv.w*xvv.w;

    __shared__ float red[16];
    #pragma unroll
    for (int o = 16; o; o >>= 1) {
        s  += __shfl_xor_sync(0xffffffffu, s,  o);
        sq += __shfl_xor_sync(0xffffffffu, sq, o);
    }
    int wid = t >> 5, lid = t & 31;
    if (lid == 0) { red[wid] = s; red[8 + wid] = sq; }
    __syncthreads();
    if (t == 0) {
        float S = 0.f, SQ = 0.f;
        #pragma unroll
        for (int i = 0; i < 8; i++) { S += red[i]; SQ += red[8 + i]; }
        red[0] = S; red[8] = SQ;
    }
    __syncthreads();
    float mu  = red[0] * (1.f / DIM);
    float var = red[8] * (1.f / DIM) - mu * mu;
    float inv = rsqrtf(var + 1e-5f);

    float4 gv = ((const float4*)g)[t];
    float4 bv = ((const float4*)b)[t];
    uint2 o;
    o.x = packh2((xvv.x - mu) * inv * gv.x + bv.x, (xvv.y - mu) * inv * gv.y + bv.y);
    o.y = packh2((xvv.z - mu) * inv * gv.z + bv.z, (xvv.w - mu) * inv * gv.w + bv.w);
    ((uint2*)(y + (size_t)row * DIM))[t] = o;
}

// ---------------- Projection GEMM v6: 4 warps x 64x64 tiles, 2 CTAs/SM -------
// Block 128x128, BK=64, 128 threads. Per kk: 4KB smem reads -> 32 wmma
// (1:2 smem:tensor). Two independent CTAs/SM decouple barrier stalls.
#define PBM 128
#define PBN 128
#define PBK 64
#define PLDH 72
#define PASZ (PBM*PLDH)
#define PBSZ (PBN*PLDH)
#define PSTG (PASZ+PBSZ)
#define PROJ_SMEM (2*PSTG*2)     // 73,728 B

__global__ __launch_bounds__(128, 2) void proj_kernel(
    const __half* __restrict__ Xt, const __half* __restrict__ Xv,
    const __half* __restrict__ Wbase,
    const float* bq1, const float* bk1, const float* bv1,
    const float* bq2, const float* bk2, const float* bv2,
    __half* tq, __half* tk, __half* tv,
    __half* vq, __half* vk, __half* vv)
{
    int z = blockIdx.z;
    bool is_text = z < 3;
    int seqlen = is_text ? NT : NV;
    if (is_text && blockIdx.y >= (BATCH*NT)/PBM) return;

    const __half* X = is_text ? Xt : Xv;
    const __half* W = Wbase + (size_t)z * DIM * DIM;
    int zz = is_text ? z : z - 3;
    const float* bias = is_text ? (zz == 0 ? bq1 : zz == 1 ? bk1 : bv1)
                                : (zz == 0 ? bq2 : zz == 1 ? bk2 : bv2);
    __half* out       = is_text ? (zz == 0 ? tq : zz == 1 ? tk : tv)
                                : (zz == 0 ? vq : zz == 1 ? vk : vv);

    extern __shared__ char smraw[];
    __half* sm = (__half*)smraw;
    float* Csh = (float*)smraw;              // epilogue alias, ld=132

    int t = threadIdx.x;                     // 0..127
    int row0 = blockIdx.y * PBM;
    int col0 = blockIdx.x * PBN;
    int wid = t >> 5;
    int warpM = wid >> 1;                    // 0..1 : 64-row slab
    int warpN = wid & 1;                     // 0..1 : 64-col slab

    wmma::fragment<wmma::accumulator, 16, 16, 16, float> acc[4][4];
    #pragma unroll
    for (int mi = 0; mi < 4; mi++)
        #pragma unroll
        for (int nj = 0; nj < 4; nj++)
            wmma::fill_fragment(acc[mi][nj], 0.0f);

    auto stage = [&](int s, int k0) {
        __half* Ad = sm + s * PSTG;
        __half* Bd = Ad + PASZ;
        #pragma unroll
        for (int i = 0; i < 8; i++) {
            int f = t + i * 128;             // 0..1023 (A: 128 rows x 8 chunks)
            int r = f >> 3, c = (f & 7) * 8;
            cp_async16(Ad + r*PLDH + c, X + (size_t)(row0 + r)*DIM + k0 + c);
        }
        #pragma unroll
        for (int i = 0; i < 8; i++) {
            int f = t + i * 128;             // B: 128 rows x 8 chunks
            int r = f >> 3, c = (f & 7) * 8;
            cp_async16(Bd + r*PLDH + c, W + (size_t)(col0 + r)*DIM + k0 + c);
        }
    };

    stage(0, 0);
    cp_commit();

    #pragma unroll 1
    for (int kt = 0; kt < DIM/PBK; kt++) {
        int buf = kt & 1;
        if (kt + 1 < DIM/PBK) {
            stage(buf ^ 1, (kt + 1) * PBK);
            cp_commit();
            cp_wait<1>();
        } else {
            cp_wait<0>();
        }
        __syncthreads();

        __half* A = sm + buf * PSTG;
        __half* B = A + PASZ;
        #pragma unroll
        for (int kk = 0; kk < 4; kk++) {
            wmma::fragment<wmma::matrix_a, 16, 16, 16, __half, wmma::row_major> a[4];
            wmma::fragment<wmma::matrix_b, 16, 16, 16, __half, wmma::col_major> bf[4];
            #pragma unroll
            for (int mi = 0; mi < 4; mi++)
                wmma::load_matrix_sync(a[mi], A + (warpM*64 + mi*16)*PLDH + kk*16, PLDH);
            #pragma unroll
            for (int nj = 0; nj < 4; nj++)
                wmma::load_matrix_sync(bf[nj], B + (warpN*64 + nj*16)*PLDH + kk*16, PLDH);
            #pragma unroll
            for (int mi = 0; mi < 4; mi++)
                #pragma unroll
                for (int nj = 0; nj < 4; nj++)
                    wmma::mma_sync(acc[mi][nj], a[mi], bf[nj], acc[mi][nj]);
        }
        __syncthreads();
    }

    // epilogue: acc -> Csh (fp32) -> bias + fp16 store with head scatter
    #pragma unroll
    for (int mi = 0; mi < 4; mi++)
        #pragma unroll
        for (int nj = 0; nj < 4; nj++)
            wmma::store_matrix_sync(Csh + (warpM*64 + mi*16)*132 + warpN*64 + nj*16,
                                    acc[mi][nj], 132, wmma::mem_row_major);
    __syncthreads();

    bool is_v = (zz == 2);
    #pragma unroll
    for (int i = 0; i < 32; i++) {
        int f = t + i * 128;                 // 0..4095 float4s over 128x128
        int r = f >> 5, c = (f & 31) * 4;
        float4 v = *(float4*)(Csh + r*132 + c);
        int jg = col0 + c;
        float4 bb = *(const float4*)(bias + jg);
        v.x += bb.x; v.y += bb.y; v.z += bb.z; v.w += bb.w;
        int gr = row0 + r;
        int bidx = gr / seqlen;
        int n = gr - bidx * seqlen;
        int h = jg >> 6;
        int d = jg & 63;
        int bh = bidx * HEADS + h;
        if (!is_v) {
            uint2 o;
            o.x = packh2(v.x, v.y);
            o.y = packh2(v.z, v.w);
            *(uint2*)(out + ((size_t)bh * seqlen + n) * DK + d) = o;
        } else {
            __half* vt = out + ((size_t)bh * DK + d) * seqlen + n;
            vt[0]        = __float2half_rn(v.x);
            vt[seqlen]   = __float2half_rn(v.y);
            vt[2*seqlen] = __float2half_rn(v.z);
            vt[3*seqlen] = __float2half_rn(v.w);
        }
    }
}

// ---------------- Flash cross-attention v8: warp M=32, lazy O-rescale --------
#define QLDH 72
#define KLDH 72
#define VLDH 72
#define AQ_SZ  (128*QLDH)
#define AK_SZ  (64*KLDH)
#define AV_SZ  (64*VLDH)
#define ATT_SMEM ((AQ_SZ + 2*AK_SZ + 2*AV_SZ) * 2)   // 55,296 B

__global__ __launch_bounds__(128, 2) void attn_kernel(
    const __half* __restrict__ tq, const __half* __restrict__ tk, const __half* __restrict__ tv,
    const __half* __restrict__ vq, const __half* __restrict__ vk, const __half* __restrict__ vv,
    float* __restrict__ outbase)
{
    int z = blockIdx.z;
    int nq = z == 0 ? NT : NV;
    int nk = z == 0 ? NV : NT;
    if (blockIdx.x >= (nq >> 7)) return;
    const __half* Qg  = z == 0 ? tq : vq;
    const __half* Kg  = z == 0 ? vk : tk;
    const __half* Vtg = z == 0 ? vv : tv;
    float* out = outbase + (z == 0 ? 0 : (size_t)BATCH*NT*DIM);

    extern __shared__ char smraw[];
    __half* smh  = (__half*)smraw;
    __half* Qsh  = smh;
    __half* Ksh0 = smh + AQ_SZ;
    __half* Vsh0 = Ksh0 + 2*AK_SZ;

    int t = threadIdx.x;          // 0..127
    int w = t >> 5;               // 0..3 -> q rows [w*32, w*32+32)
    int lane = t & 31;
    int g = lane >> 2;
    int tig = lane & 3;
    int bh = blockIdx.y;
    int q0 = blockIdx.x * 128;

    const __half* Qb  = Qg  + ((size_t)bh * nq + q0) * DK;
    const __half* Kb  = Kg  + (size_t)bh * nk * DK;
    const __half* Vtb = Vtg + (size_t)bh * DK * nk;   // [d][kv]

    #pragma unroll
    for (int i = 0; i < 8; i++) {
        int f = t + i * 128;                 // 0..1023 16B-chunks (Q)
        int r = f >> 3, c = (f & 7) * 8;
        cp_async16(Qsh + r*QLDH + c, Qb + (size_t)r*DK + c);
    }
    #pragma unroll
    for (int i = 0; i < 4; i++) {
        int f = t + i * 128;                 // 0..511 (K, Vt)
        int r = f >> 3, c = (f & 7) * 8;
        cp_async16(Ksh0 + r*KLDH + c, Kb + (size_t)r*DK + c);
        cp_async16(Vsh0 + r*VLDH + c, Vtb + (size_t)r*nk + c);
    }
    cp_commit();
    cp_wait<0>();
    __syncthreads();

    // Q fragments: 2 m-sets x 4 k-blocks; scale 1/8 folded in (exact)
    unsigned qa[2][4][4];
    #pragma unroll
    for (int set = 0; set < 2; set++) {
        const __half2 sc = __float2half2_rn(0.125f);
        const __half* q0p = Qsh + (w*32 + set*16 + g) * QLDH;
        const __half* q1p = Qsh + (w*32 + set*16 + g + 8) * QLDH;
        #pragma unroll
        for (int j = 0; j < 4; j++) {
            __half2 a0 = __hmul2(*(const __half2*)(q0p + 16*j + 2*tig), sc);
            __half2 a1 = __hmul2(*(const __half2*)(q1p + 16*j + 2*tig), sc);
            __half2 a2 = __hmul2(*(const __half2*)(q0p + 16*j + 8 + 2*tig), sc);
            __half2 a3 = __hmul2(*(const __half2*)(q1p + 16*j + 8 + 2*tig), sc);
            qa[set][j][0] = *(unsigned*)&a0;
            qa[set][j][1] = *(unsigned*)&a1;
            qa[set][j][2] = *(unsigned*)&a2;
            qa[set][j][3] = *(unsigned*)&a3;
        }
    }

    unsigned lrow = 8*((lane >> 4) & 1) + (lane & 7);
    unsigned lcol = ((lane >> 3) & 1) * 16;   // bytes

    float o[2][8][4];
    #pragma unroll
    for (int set = 0; set < 2; set++)
        #pragma unroll
        for (int n = 0; n < 8; n++)
            #pragma unroll
            for (int e = 0; e < 4; e++) o[set][n][e] = 0.f;
    float m0[2] = {-1e30f, -1e30f}, m1[2] = {-1e30f, -1e30f};
    float l0[2] = {0.f, 0.f},       l1[2] = {0.f, 0.f};

    int nch = nk >> 6;
    #pragma unroll 1
    for (int c = 0; c < nch; c++) {
        int buf = c & 1;
        if (c + 1 < nch) {
            const __half* Kc  = Kb  + (size_t)(c + 1) * 64 * DK;
            const __half* Vtc = Vtb + (size_t)(c + 1) * 64;
            __half* Kd = Ksh0 + (buf ^ 1) * AK_SZ;
            __half* Vd = Vsh0 + (buf ^ 1) * AV_SZ;
            #pragma unroll
            for (int i = 0; i < 4; i++) {
                int f = t + i * 128;
                int r = f >> 3, cc = (f & 7) * 8;
                cp_async16(Kd + r*KLDH + cc, Kc  + (size_t)r*DK + cc);
                cp_async16(Vd + r*VLDH + cc, Vtc + (size_t)r*nk + cc);
            }
            cp_commit();
            cp_wait<1>();
        } else {
            cp_wait<0>();
        }
        __syncthreads();

        const __half* K = Ksh0 + buf * AK_SZ;
        const __half* V = Vsh0 + buf * AV_SZ;
        unsigned kbase = (unsigned)__cvta_generic_to_shared(K) + lrow*KLDH*2 + lcol;
        unsigned vbase = (unsigned)__cvta_generic_to_shared(V) + lrow*VLDH*2 + lcol;

        // ---- S = Q @ K^T : each ldmat4 feeds 4 MMAs -------------------------
        float s[2][8][4];
        #pragma unroll
        for (int set = 0; set < 2; set++)
            #pragma unroll
            for (int n = 0; n < 8; n++) {
                s[set][n][0] = 0.f; s[set][n][1] = 0.f;
                s[set][n][2] = 0.f; s[set][n][3] = 0.f;
            }
        #pragma unroll
        for (int j = 0; j < 4; j++) {
            #pragma unroll
            for (int a = 0; a < 4; a++) {
                unsigned b0, b1, b2, b3;
                ldmat4(b0, b1, b2, b3, kbase + (16*a*KLDH + 16*j)*2);
                mma_f16(s[0][2*a],   qa[0][j], b0, b1);
                mma_f16(s[0][2*a+1], qa[0][j], b2, b3);
                mma_f16(s[1][2*a],   qa[1][j], b0, b1);
                mma_f16(s[1][2*a+1], qa[1][j], b2, b3);
            }
        }

        // ---- online softmax (per m-set), lazy O rescale ---------------------
        unsigned pa[2][4][4];
        #pragma unroll
        for (int set = 0; set < 2; set++) {
            float mx0 = m0[set], mx1 = m1[set];
            #pragma unroll
            for (int n = 0; n < 8; n++) {
                mx0 = fmaxf(mx0, fmaxf(s[set][n][0], s[set][n][1]));
                mx1 = fmaxf(mx1, fmaxf(s[set][n][2], s[set][n][3]));
            }
            mx0 = fmaxf(mx0, __shfl_xor_sync(0xffffffffu, mx0, 1));
            mx0 = fmaxf(mx0, __shfl_xor_sync(0xffffffffu, mx0, 2));
            mx1 = fmaxf(mx1, __shfl_xor_sync(0xffffffffu, mx1, 1));
            mx1 = fmaxf(mx1, __shfl_xor_sync(0xffffffffu, mx1, 2));
            float alpha0 = __expf(m0[set] - mx0);
            float alpha1 = __expf(m1[set] - mx1);
            m0[set] = mx0; m1[set] = mx1;

            float sum0 = 0.f, sum1 = 0.f;
            #pragma unroll
            for (int n = 0; n < 8; n++) {
                float p0 = __expf(s[set][n][0] - mx0);
                float p1 = __expf(s[set][n][1] - mx0);
                float p2 = __expf(s[set][n][2] - mx1);
                float p3 = __expf(s[set][n][3] - mx1);
                sum0 += p0 + p1; sum1 += p2 + p3;
                s[set][n][0] = p0; s[set][n][1] = p1;
                s[set][n][2] = p2; s[set][n][3] = p3;
            }
            #pragma unroll
            for (int j = 0; j < 4; j++) {
                pa[set][j][0] = packh2(s[set][2*j][0],   s[set][2*j][1]);
                pa[set][j][1] = packh2(s[set][2*j][2],   s[set][2*j][3]);
                pa[set][j][2] = packh2(s[set][2*j+1][0], s[set][2*j+1][1]);
                pa[set][j][3] = packh2(s[set][2*j+1][2], s[set][2*j+1][3]);
            }
            sum0 += __shfl_xor_sync(0xffffffffu, sum0, 1);
            sum0 += __shfl_xor_sync(0xffffffffu, sum0, 2);
            sum1 += __shfl_xor_sync(0xffffffffu, sum1, 1);
            sum1 += __shfl_xor_sync(0xffffffffu, sum1, 2);
            l0[set] = l0[set] * alpha0 + sum0;
            l1[set] = l1[set] * alpha1 + sum1;

            // skip the 64-multiply rescale when the whole warp kept its max
            if (!__all_sync(0xffffffffu, (alpha0 == 1.f) & (alpha1 == 1.f))) {
                #pragma unroll
                for (int n = 0; n < 8; n++) {
                    o[set][n][0] *= alpha0; o[set][n][1] *= alpha0;
                    o[set][n][2] *= alpha1; o[set][n][3] *= alpha1;
                }
            }
        }

        // ---- O += P @ V : each ldmat4 feeds 4 MMAs --------------------------
        #pragma unroll
        for (int j = 0; j < 4; j++) {
            #pragma unroll
            for (int a = 0; a < 4; a++) {
                unsigned b0, b1, b2, b3;
                ldmat4(b0, b1, b2, b3, vbase + (16*a*VLDH + 16*j)*2);
                mma_f16(o[0][2*a],   pa[0][j], b0, b1);
                mma_f16(o[0][2*a+1], pa[0][j], b2, b3);
                mma_f16(o[1][2*a],   pa[1][j], b0, b1);
                mma_f16(o[1][2*a+1], pa[1][j], b2, b3);
            }
        }
        __syncthreads();
    }

    // ---- epilogue: normalize + merge heads ----------------------------------
    int b = bh >> 4, h = bh & 15;
    #pragma unroll
    for (int set = 0; set < 2; set++) {
        float inv0 = 1.f / l0[set];
        float inv1 = 1.f / l1[set];
        float* ob = out + ((size_t)(b * nq) + q0 + w*32 + set*16) * DIM + h * DK;
        #pragma unroll
        for (int n = 0; n < 8; n++) {
            float2 v0 = make_float2(o[set][n][0] * inv0, o[set][n][1] * inv0);
            float2 v1 = make_float2(o[set][n][2] * inv1, o[set][n][3] * inv1);
            *(float2*)(ob + (size_t)g * DIM + 8*n + 2*tig) = v0;
            *(float2*)(ob + (size_t)(g + 8) * DIM + 8*n + 2*tig) = v1;
        }
    }
}

// ---------------- host launch ------------------------------------------------
extern "C" void kernel_launch(void* const* d_in, const int* in_sizes, int n_in,
                              void* d_out, int out_size)
{
    (void)in_sizes; (void)n_in; (void)out_size;
    const float* text   = (const float*)d_in[0];
    const float* vision = (const float*)d_in[1];
    const float* n1g = (const float*)d_in[2];
    const float* n1b = (const float*)d_in[3];
    const float* n2g = (const float*)d_in[4];
    const float* n2b = (const float*)d_in[5];
    const float* Wq1 = (const float*)d_in[6];
    const float* bq1 = (const float*)d_in[7];
    const float* Wk1 = (const float*)d_in[8];
    const float* bk1 = (const float*)d_in[9];
    const float* Wv1 = (const float*)d_in[10];
    const float* bv1 = (const float*)d_in[11];
    const float* Wq2 = (const float*)d_in[12];
    const float* bq2 = (const float*)d_in[13];
    const float* Wk2 = (const float*)d_in[14];
    const float* bk2 = (const float*)d_in[15];
    const float* Wv2 = (const float*)d_in[16];
    const float* bv2 = (const float*)d_in[17];
    float* out = (float*)d_out;

    __half *tn, *vn, *tq, *tk, *tv, *vq, *vk, *vv, *wc;
    cudaGetSymbolAddress((void**)&tn, g_tn);
    cudaGetSymbolAddress((void**)&vn, g_vn);
    cudaGetSymbolAddress((void**)&tq, g_tq);
    cudaGetSymbolAddress((void**)&tk, g_tk);
    cudaGetSymbolAddress((void**)&tv, g_tv);
    cudaGetSymbolAddress((void**)&vq, g_vq);
    cudaGetSymbolAddress((void**)&vk, g_vk);
    cudaGetSymbolAddress((void**)&vv, g_vv);
    cudaGetSymbolAddress((void**)&wc, g_wc);

    const size_t A1 = (size_t)BATCH * NT * DIM;
    const size_t A2 = (size_t)BATCH * NV * DIM;
    const size_t WSZ = (size_t)DIM * DIM;

    // fp16 weights (one launch)
    half_conv_kernel<<<dim3(WSZ / (256*4), 6), 256>>>(Wq1, Wk1, Wv1, Wq2, Wk2, Wv2, wc);

    // both layernorms + residual passthrough, one launch
    ln_kernel<<<dim3(BATCH * NV, 2), 256>>>(text, vision, n1g, n1b, n2g, n2b,
                                            tn, vn,
                                            out + A1 + A2, out + A1 + A2 + A1);

    // all six projections, one launch (128-thread CTAs)
    cudaFuncSetAttribute(proj_kernel, cudaFuncAttributeMaxDynamicSharedMemorySize, PROJ_SMEM);
    dim3 gp(DIM / PBN, BATCH * NV / PBM, 6);
    proj_kernel<<<gp, 128, PROJ_SMEM>>>(tn, vn, wc,
                                        bq1, bk1, bv1, bq2, bk2, bv2,
                                        tq, tk, tv, vq, vk, vv);

    // both attention directions, one launch
    cudaFuncSetAttribute(attn_kernel, cudaFuncAttributeMaxDynamicSharedMemorySize, ATT_SMEM);
    dim3 ga(NV / 128, BH, 2);
    attn_kernel<<<ga, 128, ATT_SMEM>>>(tq, tk, tv, vq, vk, vv, out);
}